// round 4
// baseline (speedup 1.0000x reference)
#include <cuda_runtime.h>

#define BATCH 4
#define NB 262144
#define NA 8192
#define FDIM 32
#define HID 64
#define OUT 32

__device__ __align__(16) float g_AP1[BATCH * NA * HID];
__device__ __align__(16) float g_AP2[BATCH * NA * HID];
__device__ __align__(16) float g_accum[BATCH * NA * OUT];
__device__ int   g_count[BATCH * NA];
__device__ float g_bsum[BATCH * OUT];
__device__ float g_asum[BATCH * OUT];
__device__ float g_hb[BATCH * HID];

__device__ __forceinline__ float softplus_f(float x) {
    float e = __expf(-fabsf(x));
    return fmaxf(x, 0.0f) + __logf(1.0f + e);
}

typedef unsigned long long ull;
__device__ __forceinline__ ull pack2(float lo, float hi) {
    ull d; asm("mov.b64 %0, {%1, %2};" : "=l"(d) : "f"(lo), "f"(hi)); return d;
}
__device__ __forceinline__ void unpack2(ull p, float& lo, float& hi) {
    asm("mov.b64 {%0, %1}, %2;" : "=f"(lo), "=f"(hi) : "l"(p));
}
__device__ __forceinline__ ull fma2(ull a, ull b, ull c) {
    ull d; asm("fma.rn.f32x2 %0, %1, %2, %3;" : "=l"(d) : "l"(a), "l"(b), "l"(c)); return d;
}

__global__ void zero_kernel() {
    int t = blockIdx.x * blockDim.x + threadIdx.x;
    int n = gridDim.x * blockDim.x;
    for (int i = t; i < BATCH * NA * OUT; i += n) g_accum[i] = 0.0f;
    for (int i = t; i < BATCH * NA; i += n) g_count[i] = 0;
    if (t < BATCH * OUT) { g_bsum[t] = 0.0f; g_asum[t] = 0.0f; }
}

__global__ void hb_kernel(const float* __restrict__ state,
                          const float* __restrict__ ew1,
                          const float* __restrict__ eb1) {
    int t = threadIdx.x;
    int b = t >> 6, j = t & 63;
    float acc = eb1[j];
    for (int i = 0; i < FDIM; ++i)
        acc = fmaf(state[b * FDIM + i], ew1[(96 + i) * HID + j], acc);
    g_hb[b * HID + j] = acc;
}

// per-atom precompute: AP1 = atoms @ e_w1[0:32,:], AP2 = atoms @ e_w1[32:64,:]
__global__ void ap_kernel(const float* __restrict__ atoms,
                          const float* __restrict__ ew1) {
    extern __shared__ float sm[];
    float* sW = sm;                  // 64*64
    float* scratch = sm + 64 * HID;  // 128*33
    int tid = threadIdx.x;
    for (int i = tid; i < 64 * HID; i += blockDim.x) sW[i] = ew1[i];
    __syncthreads();
    int a = blockIdx.x * blockDim.x + tid;
    float* row = scratch + tid * 33;
    const float4* arow = reinterpret_cast<const float4*>(atoms + (size_t)a * FDIM);
#pragma unroll
    for (int k = 0; k < 8; ++k) {
        float4 v = arow[k];
        row[4*k] = v.x; row[4*k+1] = v.y; row[4*k+2] = v.z; row[4*k+3] = v.w;
    }
    for (int half = 0; half < 2; ++half) {
        float acc[HID];
#pragma unroll
        for (int j = 0; j < HID; ++j) acc[j] = 0.0f;
        for (int i = 0; i < 32; ++i) {
            float xv = row[i];
            const float4* w = reinterpret_cast<const float4*>(sW + (half * 32 + i) * HID);
#pragma unroll
            for (int j4 = 0; j4 < 16; ++j4) {
                float4 wv = w[j4];
                acc[4*j4]   = fmaf(xv, wv.x, acc[4*j4]);
                acc[4*j4+1] = fmaf(xv, wv.y, acc[4*j4+1]);
                acc[4*j4+2] = fmaf(xv, wv.z, acc[4*j4+2]);
                acc[4*j4+3] = fmaf(xv, wv.w, acc[4*j4+3]);
            }
        }
        float* dst = (half == 0 ? g_AP1 : g_AP2) + (size_t)a * HID;
        float4* o = reinterpret_cast<float4*>(dst);
#pragma unroll
        for (int j4 = 0; j4 < 16; ++j4)
            o[j4] = make_float4(acc[4*j4], acc[4*j4+1], acc[4*j4+2], acc[4*j4+3]);
    }
}

// ---------------- bond MLP: warp-uniform-output tiled GEMM, f32x2 ----------------
__global__ void __launch_bounds__(128) bond_kernel(
        const float* __restrict__ bonds,
        const int* __restrict__ ia1,
        const int* __restrict__ ia2,
        const float* __restrict__ ew1,
        const float* __restrict__ eb2,
        const float* __restrict__ ew2,
        const float* __restrict__ ew3,
        const float* __restrict__ eb3,
        float* __restrict__ out) {
    extern __shared__ __align__(16) float sm[];
    float* sW1b = sm;               // 32*64 rows 64..95 of e_w1 (bond part)
    float* sW2  = sm + 2048;        // 64*64
    float* sW3  = sm + 6144;        // 64*32
    float* sX   = sm + 8192;        // 64 rows x 128 bonds (transposed acts)
    float* sHb  = sm + 16384;       // 64
    float* sB2  = sm + 16448;       // 64
    float* sB3  = sm + 16512;       // 32
    int*   sIa1 = (int*)(sm + 16544); // 128
    int*   sIa2 = sIa1 + 128;         // 128

    const int tid  = threadIdx.x;
    const int lane = tid & 31;
    const int w    = tid >> 5;        // warp id 0..3
    const int base = blockIdx.x * 128;
    const int batch = base >> 18;

    for (int i = tid; i < 32 * HID; i += 128) sW1b[i] = ew1[64 * HID + i];
    for (int i = tid; i < HID * HID; i += 128) sW2[i] = ew2[i];
    for (int i = tid; i < HID * OUT; i += 128) sW3[i] = ew3[i];
    if (tid < HID) { sHb[tid] = g_hb[batch * HID + tid]; sB2[tid] = eb2[tid]; }
    if (tid < OUT) sB3[tid] = eb3[tid];
    sIa1[tid] = ia1[base + tid];
    sIa2[tid] = ia2[base + tid];
    // stage X0^T: thread tid owns bond tid; scalar stores hit 32 distinct banks
    {
        const float4* brow = reinterpret_cast<const float4*>(bonds + (size_t)(base + tid) * FDIM);
#pragma unroll
        for (int k4 = 0; k4 < 8; ++k4) {
            float4 v = brow[k4];
            sX[(4*k4+0) * 128 + tid] = v.x;
            sX[(4*k4+1) * 128 + tid] = v.y;
            sX[(4*k4+2) * 128 + tid] = v.z;
            sX[(4*k4+3) * 128 + tid] = v.w;
        }
    }
    __syncthreads();

    const int ob = w * 16;   // this warp's output base (layers 1,2)
    ull acc[4][8];

    // ----- layer 1: init = AP1[a1] + AP2[a2] + hb -----
    {
        float hbv[16];
#pragma unroll
        for (int i = 0; i < 16; i += 4) {
            float4 h4 = *reinterpret_cast<float4*>(&sHb[ob + i]);
            hbv[i] = h4.x; hbv[i+1] = h4.y; hbv[i+2] = h4.z; hbv[i+3] = h4.w;
        }
#pragma unroll
        for (int bb = 0; bb < 4; ++bb) {
            int bl = lane * 4 + bb;
            const float4* p1 = reinterpret_cast<const float4*>(
                g_AP1 + ((size_t)batch * NA + sIa1[bl]) * HID + ob);
            const float4* p2 = reinterpret_cast<const float4*>(
                g_AP2 + ((size_t)batch * NA + sIa2[bl]) * HID + ob);
#pragma unroll
            for (int q = 0; q < 4; ++q) {
                float4 u = p1[q], v = p2[q];
                acc[bb][2*q]   = pack2(u.x + v.x + hbv[4*q],   u.y + v.y + hbv[4*q+1]);
                acc[bb][2*q+1] = pack2(u.z + v.z + hbv[4*q+2], u.w + v.w + hbv[4*q+3]);
            }
        }
    }
#pragma unroll 4
    for (int k = 0; k < 32; ++k) {
        const ulonglong2* wr = reinterpret_cast<const ulonglong2*>(&sW1b[k * HID + ob]);
        ulonglong2 w0 = wr[0], w1 = wr[1], w2 = wr[2], w3 = wr[3];
        ull wp[8] = {w0.x, w0.y, w1.x, w1.y, w2.x, w2.y, w3.x, w3.y};
        float4 xv = *reinterpret_cast<float4*>(&sX[k * 128 + lane * 4]);
        ull xd[4] = {pack2(xv.x, xv.x), pack2(xv.y, xv.y), pack2(xv.z, xv.z), pack2(xv.w, xv.w)};
#pragma unroll
        for (int bb = 0; bb < 4; ++bb)
#pragma unroll
            for (int p = 0; p < 8; ++p) acc[bb][p] = fma2(xd[bb], wp[p], acc[bb][p]);
    }
    {
        float sv[4][16];
#pragma unroll
        for (int bb = 0; bb < 4; ++bb)
#pragma unroll
            for (int p = 0; p < 8; ++p) {
                float lo, hi; unpack2(acc[bb][p], lo, hi);
                sv[bb][2*p] = softplus_f(lo); sv[bb][2*p+1] = softplus_f(hi);
            }
        __syncthreads();
#pragma unroll
        for (int j = 0; j < 16; ++j)
            *reinterpret_cast<float4*>(&sX[(ob + j) * 128 + lane * 4]) =
                make_float4(sv[0][j], sv[1][j], sv[2][j], sv[3][j]);
    }
    __syncthreads();

    // ----- layer 2 -----
    {
        const ulonglong2* bq = reinterpret_cast<const ulonglong2*>(&sB2[ob]);
        ulonglong2 b0 = bq[0], b1 = bq[1], b2 = bq[2], b3 = bq[3];
#pragma unroll
        for (int bb = 0; bb < 4; ++bb) {
            acc[bb][0]=b0.x; acc[bb][1]=b0.y; acc[bb][2]=b1.x; acc[bb][3]=b1.y;
            acc[bb][4]=b2.x; acc[bb][5]=b2.y; acc[bb][6]=b3.x; acc[bb][7]=b3.y;
        }
    }
#pragma unroll 4
    for (int k = 0; k < 64; ++k) {
        const ulonglong2* wr = reinterpret_cast<const ulonglong2*>(&sW2[k * HID + ob]);
        ulonglong2 w0 = wr[0], w1 = wr[1], w2 = wr[2], w3 = wr[3];
        ull wp[8] = {w0.x, w0.y, w1.x, w1.y, w2.x, w2.y, w3.x, w3.y};
        float4 xv = *reinterpret_cast<float4*>(&sX[k * 128 + lane * 4]);
        ull xd[4] = {pack2(xv.x, xv.x), pack2(xv.y, xv.y), pack2(xv.z, xv.z), pack2(xv.w, xv.w)};
#pragma unroll
        for (int bb = 0; bb < 4; ++bb)
#pragma unroll
            for (int p = 0; p < 8; ++p) acc[bb][p] = fma2(xd[bb], wp[p], acc[bb][p]);
    }
    {
        float sv[4][16];
#pragma unroll
        for (int bb = 0; bb < 4; ++bb)
#pragma unroll
            for (int p = 0; p < 8; ++p) {
                float lo, hi; unpack2(acc[bb][p], lo, hi);
                sv[bb][2*p] = softplus_f(lo); sv[bb][2*p+1] = softplus_f(hi);
            }
        __syncthreads();
#pragma unroll
        for (int j = 0; j < 16; ++j)
            *reinterpret_cast<float4*>(&sX[(ob + j) * 128 + lane * 4]) =
                make_float4(sv[0][j], sv[1][j], sv[2][j], sv[3][j]);
    }
    __syncthreads();

    // ----- layer 3 (64 -> 32): warp owns outputs [w*8, w*8+8) -----
    {
        const int o3 = w * 8;
        ull a3[4][4];
        {
            const ulonglong2* bq = reinterpret_cast<const ulonglong2*>(&sB3[o3]);
            ulonglong2 b0 = bq[0], b1 = bq[1];
#pragma unroll
            for (int bb = 0; bb < 4; ++bb) {
                a3[bb][0]=b0.x; a3[bb][1]=b0.y; a3[bb][2]=b1.x; a3[bb][3]=b1.y;
            }
        }
#pragma unroll 4
        for (int k = 0; k < 64; ++k) {
            const ulonglong2* wr = reinterpret_cast<const ulonglong2*>(&sW3[k * OUT + o3]);
            ulonglong2 w0 = wr[0], w1 = wr[1];
            ull wp[4] = {w0.x, w0.y, w1.x, w1.y};
            float4 xv = *reinterpret_cast<float4*>(&sX[k * 128 + lane * 4]);
            ull xd[4] = {pack2(xv.x, xv.x), pack2(xv.y, xv.y), pack2(xv.z, xv.z), pack2(xv.w, xv.w)};
#pragma unroll
            for (int bb = 0; bb < 4; ++bb)
#pragma unroll
                for (int p = 0; p < 4; ++p) a3[bb][p] = fma2(xd[bb], wp[p], a3[bb][p]);
        }
        float sv[4][8];
#pragma unroll
        for (int bb = 0; bb < 4; ++bb)
#pragma unroll
            for (int p = 0; p < 4; ++p) {
                float lo, hi; unpack2(a3[bb][p], lo, hi);
                sv[bb][2*p] = softplus_f(lo); sv[bb][2*p+1] = softplus_f(hi);
            }
#pragma unroll
        for (int bb = 0; bb < 4; ++bb) {
            int bl = lane * 4 + bb;
            size_t g = (size_t)(base + bl);
            float4* orow = reinterpret_cast<float4*>(out + g * OUT + o3);
            orow[0] = make_float4(sv[bb][0], sv[bb][1], sv[bb][2], sv[bb][3]);
            orow[1] = make_float4(sv[bb][4], sv[bb][5], sv[bb][6], sv[bb][7]);
            int a1 = sIa1[bl];
            float* ap = g_accum + ((size_t)batch * NA + a1) * OUT + o3;
#pragma unroll
            for (int j = 0; j < 8; ++j) atomicAdd(ap + j, sv[bb][j]);
            if (w == 0) atomicAdd(&g_count[batch * NA + a1], 1);
        }
        // per-batch bond-output mean partial (warp outputs disjoint)
        float s8[8];
#pragma unroll
        for (int j = 0; j < 8; ++j)
            s8[j] = sv[0][j] + sv[1][j] + sv[2][j] + sv[3][j];
#pragma unroll
        for (int j = 0; j < 8; ++j) {
            float v = s8[j];
            v += __shfl_xor_sync(0xffffffffu, v, 16);
            v += __shfl_xor_sync(0xffffffffu, v, 8);
            v += __shfl_xor_sync(0xffffffffu, v, 4);
            v += __shfl_xor_sync(0xffffffffu, v, 2);
            v += __shfl_xor_sync(0xffffffffu, v, 1);
            if (lane == 0) atomicAdd(&g_bsum[batch * OUT + o3 + j], v);
        }
    }
}

// ---------------- atom MLP (per-thread; ~3% of total work) ----------------
__global__ void atom_kernel(const float* __restrict__ atoms,
                            const float* __restrict__ state,
                            const float* __restrict__ vw1,
                            const float* __restrict__ vb1,
                            const float* __restrict__ vw2,
                            const float* __restrict__ vb2,
                            const float* __restrict__ vw3,
                            const float* __restrict__ vb3,
                            float* __restrict__ out) {
    extern __shared__ float sm[];
    float* sW1 = sm;                    // 96*64
    float* sW2 = sW1 + 96 * HID;        // 64*64
    float* sW3 = sW2 + HID * HID;       // 64*32
    float* scratch = sW3 + HID * OUT;   // 128*97
    float* sB1 = scratch + 128 * 97;
    float* sB2 = sB1 + HID;
    float* sB3 = sB2 + HID;
    float* sMsum = sB3 + OUT;

    int tid = threadIdx.x;
    int a = blockIdx.x * 128 + tid;
    int b = a >> 13;

    for (int i = tid; i < 96 * HID; i += 128) sW1[i] = vw1[i];
    for (int i = tid; i < HID * HID; i += 128) sW2[i] = vw2[i];
    for (int i = tid; i < HID * OUT; i += 128) sW3[i] = vw3[i];
    if (tid < HID) { sB1[tid] = vb1[tid]; sB2[tid] = vb2[tid]; }
    if (tid < OUT) { sB3[tid] = vb3[tid]; sMsum[tid] = 0.0f; }
    __syncthreads();

    float* row = scratch + tid * 97;
    float inv = 1.0f / (float)g_count[a];
    const float4* pa = reinterpret_cast<const float4*>(g_accum + (size_t)a * OUT);
#pragma unroll
    for (int k = 0; k < 8; ++k) {
        float4 v = pa[k];
        row[4*k] = v.x*inv; row[4*k+1] = v.y*inv; row[4*k+2] = v.z*inv; row[4*k+3] = v.w*inv;
    }
    const float4* pt = reinterpret_cast<const float4*>(atoms + (size_t)a * FDIM);
#pragma unroll
    for (int k = 0; k < 8; ++k) {
        float4 v = pt[k];
        row[32+4*k] = v.x; row[32+4*k+1] = v.y; row[32+4*k+2] = v.z; row[32+4*k+3] = v.w;
    }
    const float4* ps = reinterpret_cast<const float4*>(state + (size_t)b * FDIM);
#pragma unroll
    for (int k = 0; k < 8; ++k) {
        float4 v = ps[k];
        row[64+4*k] = v.x; row[64+4*k+1] = v.y; row[64+4*k+2] = v.z; row[64+4*k+3] = v.w;
    }

    float h[HID];
#pragma unroll
    for (int j = 0; j < HID; ++j) h[j] = sB1[j];
    for (int i = 0; i < 96; ++i) {
        float xv = row[i];
        const float4* wr = reinterpret_cast<const float4*>(sW1 + i * HID);
#pragma unroll
        for (int j4 = 0; j4 < 16; ++j4) {
            float4 wv = wr[j4];
            h[4*j4]   = fmaf(xv, wv.x, h[4*j4]);
            h[4*j4+1] = fmaf(xv, wv.y, h[4*j4+1]);
            h[4*j4+2] = fmaf(xv, wv.z, h[4*j4+2]);
            h[4*j4+3] = fmaf(xv, wv.w, h[4*j4+3]);
        }
    }
#pragma unroll
    for (int j = 0; j < HID; ++j) row[j] = softplus_f(h[j]);

    float h2[HID];
#pragma unroll
    for (int j = 0; j < HID; ++j) h2[j] = sB2[j];
    for (int i = 0; i < HID; ++i) {
        float xv = row[i];
        const float4* wr = reinterpret_cast<const float4*>(sW2 + i * HID);
#pragma unroll
        for (int j4 = 0; j4 < 16; ++j4) {
            float4 wv = wr[j4];
            h2[4*j4]   = fmaf(xv, wv.x, h2[4*j4]);
            h2[4*j4+1] = fmaf(xv, wv.y, h2[4*j4+1]);
            h2[4*j4+2] = fmaf(xv, wv.z, h2[4*j4+2]);
            h2[4*j4+3] = fmaf(xv, wv.w, h2[4*j4+3]);
        }
    }
#pragma unroll
    for (int j = 0; j < HID; ++j) row[j] = softplus_f(h2[j]);

    float h3[OUT];
#pragma unroll
    for (int j = 0; j < OUT; ++j) h3[j] = sB3[j];
    for (int i = 0; i < HID; ++i) {
        float xv = row[i];
        const float4* wr = reinterpret_cast<const float4*>(sW3 + i * OUT);
#pragma unroll
        for (int j4 = 0; j4 < 8; ++j4) {
            float4 wv = wr[j4];
            h3[4*j4]   = fmaf(xv, wv.x, h3[4*j4]);
            h3[4*j4+1] = fmaf(xv, wv.y, h3[4*j4+1]);
            h3[4*j4+2] = fmaf(xv, wv.z, h3[4*j4+2]);
            h3[4*j4+3] = fmaf(xv, wv.w, h3[4*j4+3]);
        }
    }
    float o[OUT];
#pragma unroll
    for (int j = 0; j < OUT; ++j) o[j] = softplus_f(h3[j]);

    float4* orow = reinterpret_cast<float4*>(out + (size_t)(BATCH * NB * OUT) + (size_t)a * OUT);
#pragma unroll
    for (int j4 = 0; j4 < 8; ++j4)
        orow[j4] = make_float4(o[4*j4], o[4*j4+1], o[4*j4+2], o[4*j4+3]);

    int lane = tid & 31;
#pragma unroll
    for (int j = 0; j < OUT; ++j) {
        float v = o[j];
        v += __shfl_xor_sync(0xffffffffu, v, 16);
        v += __shfl_xor_sync(0xffffffffu, v, 8);
        v += __shfl_xor_sync(0xffffffffu, v, 4);
        v += __shfl_xor_sync(0xffffffffu, v, 2);
        v += __shfl_xor_sync(0xffffffffu, v, 1);
        if (lane == 0) atomicAdd(&sMsum[j], v);
    }
    __syncthreads();
    if (tid < OUT) atomicAdd(&g_asum[b * OUT + tid], sMsum[tid]);
}

__global__ void state_kernel(const float* __restrict__ state,
                             const float* __restrict__ uw1,
                             const float* __restrict__ ub1,
                             const float* __restrict__ uw2,
                             const float* __restrict__ ub2,
                             const float* __restrict__ uw3,
                             const float* __restrict__ ub3,
                             float* __restrict__ out) {
    __shared__ float uin[96];
    __shared__ float h1s[HID];
    __shared__ float h2s[HID];
    int b = blockIdx.x;
    int j = threadIdx.x;
    if (j < 32) {
        uin[j] = g_bsum[b * OUT + j] * (1.0f / (float)NB);
        uin[32 + j] = g_asum[b * OUT + j] * (1.0f / (float)NA);
        uin[64 + j] = state[b * FDIM + j];
    }
    __syncthreads();
    float acc = ub1[j];
    for (int i = 0; i < 96; ++i) acc = fmaf(uin[i], uw1[i * HID + j], acc);
    h1s[j] = softplus_f(acc);
    __syncthreads();
    acc = ub2[j];
    for (int i = 0; i < HID; ++i) acc = fmaf(h1s[i], uw2[i * HID + j], acc);
    h2s[j] = softplus_f(acc);
    __syncthreads();
    if (j < OUT) {
        acc = ub3[j];
        for (int i = 0; i < HID; ++i) acc = fmaf(h2s[i], uw3[i * OUT + j], acc);
        out[(size_t)(BATCH * NB * OUT) + (size_t)(BATCH * NA * OUT) + b * OUT + j] = softplus_f(acc);
    }
}

extern "C" void kernel_launch(void* const* d_in, const int* in_sizes, int n_in,
                              void* d_out, int out_size) {
    const float* bonds = (const float*)d_in[0];
    const int* ia1 = (const int*)d_in[1];
    const int* ia2 = (const int*)d_in[2];
    const float* atoms = (const float*)d_in[3];
    const float* state = (const float*)d_in[4];
    const float* ew1 = (const float*)d_in[5];
    const float* eb1 = (const float*)d_in[6];
    const float* ew2 = (const float*)d_in[7];
    const float* eb2 = (const float*)d_in[8];
    const float* ew3 = (const float*)d_in[9];
    const float* eb3 = (const float*)d_in[10];
    const float* vw1 = (const float*)d_in[11];
    const float* vb1 = (const float*)d_in[12];
    const float* vw2 = (const float*)d_in[13];
    const float* vb2 = (const float*)d_in[14];
    const float* vw3 = (const float*)d_in[15];
    const float* vb3 = (const float*)d_in[16];
    const float* uw1 = (const float*)d_in[17];
    const float* ub1 = (const float*)d_in[18];
    const float* uw2 = (const float*)d_in[19];
    const float* ub2 = (const float*)d_in[20];
    const float* uw3 = (const float*)d_in[21];
    const float* ub3 = (const float*)d_in[22];
    float* out = (float*)d_out;

    const int AP_SMEM   = (64 * HID + 128 * 33) * (int)sizeof(float);
    const int BOND_SMEM = 16544 * (int)sizeof(float) + 256 * (int)sizeof(int);
    const int ATOM_SMEM = (96 * HID + HID * HID + HID * OUT + 128 * 97 + HID + HID + OUT + OUT) * (int)sizeof(float);

    cudaFuncSetAttribute(ap_kernel, cudaFuncAttributeMaxDynamicSharedMemorySize, AP_SMEM);
    cudaFuncSetAttribute(bond_kernel, cudaFuncAttributeMaxDynamicSharedMemorySize, BOND_SMEM);
    cudaFuncSetAttribute(atom_kernel, cudaFuncAttributeMaxDynamicSharedMemorySize, ATOM_SMEM);

    zero_kernel<<<1024, 256>>>();
    hb_kernel<<<1, 256>>>(state, ew1, eb1);
    ap_kernel<<<(BATCH * NA) / 128, 128, AP_SMEM>>>(atoms, ew1);
    bond_kernel<<<(BATCH * NB) / 128, 128, BOND_SMEM>>>(bonds, ia1, ia2, ew1, eb2, ew2, ew3, eb3, out);
    atom_kernel<<<(BATCH * NA) / 128, 128, ATOM_SMEM>>>(atoms, state, vw1, vb1, vw2, vb2, vw3, vb3, out);
    state_kernel<<<BATCH, 64>>>(state, uw1, ub1, uw2, ub2, uw3, ub3, out);
}

// round 8
// speedup vs baseline: 2.5107x; 2.5107x over previous
#include <cuda_runtime.h>
#include <cuda_bf16.h>
#include <cstdint>

#define BATCH 4
#define NB 262144
#define NA 8192
#define FDIM 32
#define HID 64
#define OUT 32

// bond-kernel smem byte offsets
#define O_W1 0
#define O_W2 9216
#define O_W3 26624
#define O_X  35328
#define O_HB 70144
#define O_B2 70400
#define O_B3 70656
#define O_IA1 70784
#define O_IA2 71296
#define BOND_SMEM 71808
#define W1S 144
#define W2S 272
#define W3S 272
#define XW 68   // X row stride in 4B words (272 bytes, ≡16 mod 128 -> conflict-free frags)

__device__ __align__(16) float g_AP1[BATCH * NA * HID];
__device__ __align__(16) float g_AP2[BATCH * NA * HID];
__device__ __align__(16) float g_accum[BATCH * NA * OUT];
__device__ int   g_count[BATCH * NA];
__device__ float g_bsum[BATCH * OUT];
__device__ float g_asum[BATCH * OUT];
__device__ float g_hb[BATCH * HID];
__device__ __align__(16) unsigned char g_wimg[36864]; // pre-split bf16 hi/lo weight image

__device__ __forceinline__ float softplus_f(float x) {
    float e = __expf(-fabsf(x));
    return fmaxf(x, 0.0f) + __logf(1.0f + e);
}
__device__ __forceinline__ void bsplit(float x, float& h, float& l) {
    __nv_bfloat16 hb = __float2bfloat16(x);
    h = __bfloat162float(hb);
    l = x - h;
}
// pack (a -> lo16, b -> hi16)
__device__ __forceinline__ uint32_t packbf(float a, float b) {
    uint32_t r; asm("cvt.rn.bf16x2.f32 %0, %1, %2;" : "=r"(r) : "f"(b), "f"(a)); return r;
}
__device__ __forceinline__ void mma16(float* c, uint32_t a0, uint32_t a1, uint32_t a2, uint32_t a3,
                                      uint32_t b0, uint32_t b1) {
    asm volatile("mma.sync.aligned.m16n8k16.row.col.f32.bf16.bf16.f32 "
        "{%0,%1,%2,%3}, {%4,%5,%6,%7}, {%8,%9}, {%0,%1,%2,%3};"
        : "+f"(c[0]), "+f"(c[1]), "+f"(c[2]), "+f"(c[3])
        : "r"(a0), "r"(a1), "r"(a2), "r"(a3), "r"(b0), "r"(b1));
}

// ---------------- setup kernels ----------------
__global__ void zero_kernel() {
    int t = blockIdx.x * blockDim.x + threadIdx.x;
    int n = gridDim.x * blockDim.x;
    for (int i = t; i < BATCH * NA * OUT; i += n) g_accum[i] = 0.0f;
    for (int i = t; i < BATCH * NA; i += n) g_count[i] = 0;
    if (t < BATCH * OUT) { g_bsum[t] = 0.0f; g_asum[t] = 0.0f; }
}

__global__ void hb_kernel(const float* __restrict__ state,
                          const float* __restrict__ ew1,
                          const float* __restrict__ eb1) {
    int t = threadIdx.x;
    int b = t >> 6, j = t & 63;
    float acc = eb1[j];
    for (int i = 0; i < FDIM; ++i)
        acc = fmaf(state[b * FDIM + i], ew1[(96 + i) * HID + j], acc);
    g_hb[b * HID + j] = acc;
}

// weight image: W[n][k] bf16, hi block then lo block per row
__global__ void prep_tiles(const float* __restrict__ ew1,
                           const float* __restrict__ ew2,
                           const float* __restrict__ ew3) {
    int t = threadIdx.x;
    for (int i = t; i < 64 * 32; i += 256) {     // W1: bond part of e_w1 (rows 64..95)
        int n = i >> 5, k = i & 31;
        float h, l; bsplit(ew1[(64 + k) * HID + n], h, l);
        *(__nv_bfloat16*)(g_wimg + O_W1 + n * W1S + k * 2) = __float2bfloat16(h);
        *(__nv_bfloat16*)(g_wimg + O_W1 + n * W1S + 64 + k * 2) = __float2bfloat16(l);
    }
    for (int i = t; i < 64 * 64; i += 256) {     // W2
        int n = i >> 6, k = i & 63;
        float h, l; bsplit(ew2[k * HID + n], h, l);
        *(__nv_bfloat16*)(g_wimg + O_W2 + n * W2S + k * 2) = __float2bfloat16(h);
        *(__nv_bfloat16*)(g_wimg + O_W2 + n * W2S + 128 + k * 2) = __float2bfloat16(l);
    }
    for (int i = t; i < 32 * 64; i += 256) {     // W3
        int n = i >> 6, k = i & 63;
        float h, l; bsplit(ew3[k * OUT + n], h, l);
        *(__nv_bfloat16*)(g_wimg + O_W3 + n * W3S + k * 2) = __float2bfloat16(h);
        *(__nv_bfloat16*)(g_wimg + O_W3 + n * W3S + 128 + k * 2) = __float2bfloat16(l);
    }
}

// per-atom tables: AP1 = atoms @ e_w1[0:32,:], AP2 = atoms @ e_w1[32:64,:]
__global__ void ap_kernel(const float* __restrict__ atoms,
                          const float* __restrict__ ew1) {
    extern __shared__ float sm[];
    float* sW = sm;
    float* scratch = sm + 64 * HID;
    int tid = threadIdx.x;
    for (int i = tid; i < 64 * HID; i += blockDim.x) sW[i] = ew1[i];
    __syncthreads();
    int a = blockIdx.x * blockDim.x + tid;
    float* row = scratch + tid * 33;
    const float4* arow = reinterpret_cast<const float4*>(atoms + (size_t)a * FDIM);
#pragma unroll
    for (int k = 0; k < 8; ++k) {
        float4 v = arow[k];
        row[4*k] = v.x; row[4*k+1] = v.y; row[4*k+2] = v.z; row[4*k+3] = v.w;
    }
    for (int half = 0; half < 2; ++half) {
        float acc[HID];
#pragma unroll
        for (int j = 0; j < HID; ++j) acc[j] = 0.0f;
        for (int i = 0; i < 32; ++i) {
            float xv = row[i];
            const float4* wr = reinterpret_cast<const float4*>(sW + (half * 32 + i) * HID);
#pragma unroll
            for (int j4 = 0; j4 < 16; ++j4) {
                float4 wv = wr[j4];
                acc[4*j4]   = fmaf(xv, wv.x, acc[4*j4]);
                acc[4*j4+1] = fmaf(xv, wv.y, acc[4*j4+1]);
                acc[4*j4+2] = fmaf(xv, wv.z, acc[4*j4+2]);
                acc[4*j4+3] = fmaf(xv, wv.w, acc[4*j4+3]);
            }
        }
        float4* o = reinterpret_cast<float4*>((half == 0 ? g_AP1 : g_AP2) + (size_t)a * HID);
#pragma unroll
        for (int j4 = 0; j4 < 16; ++j4)
            o[j4] = make_float4(acc[4*j4], acc[4*j4+1], acc[4*j4+2], acc[4*j4+3]);
    }
}

// ---------------- bond MLP: mma.sync bf16-split GEMM ----------------
template<int NT, int NS>
__device__ __forceinline__ void gemm_layer(float (&acc)[2][NT][4], const uint32_t* Xw,
        const unsigned char* wb, int ws, const int2* st, int w, int g, int tg) {
#pragma unroll
    for (int s = 0; s < NS; ++s) {
        int ak = st[s].x >> 1, bk = st[s].y;
        uint32_t b0[NT], b1[NT];
#pragma unroll
        for (int nt = 0; nt < NT; ++nt) {
            const uint32_t* bp = (const uint32_t*)(wb + (nt * 8 + g) * ws + bk * 2 + tg * 4);
            b0[nt] = bp[0]; b1[nt] = bp[4];
        }
#pragma unroll
        for (int t = 0; t < 2; ++t) {
            int r1 = w * 32 + t * 16 + g, r2 = r1 + 8;
            int i1 = r1 * XW + ((r1 >> 3) & 3) + ak + tg;
            int i2 = r2 * XW + ((r2 >> 3) & 3) + ak + tg;
            uint32_t a0 = Xw[i1], a2 = Xw[i1 + 4], a1 = Xw[i2], a3 = Xw[i2 + 4];
#pragma unroll
            for (int nt = 0; nt < NT; ++nt) mma16(acc[t][nt], a0, a1, a2, a3, b0[nt], b1[nt]);
        }
    }
}

template<int NT, bool HB>
__device__ __forceinline__ void epi_store(float (&acc)[2][NT][4], uint32_t* Xw,
        const float* bias, int w, int g, int tg) {
    __syncwarp();
#pragma unroll
    for (int t = 0; t < 2; ++t)
#pragma unroll
        for (int h = 0; h < 2; ++h) {
            int row = w * 32 + t * 16 + h * 8 + g;
            int rw = row * XW + ((row >> 3) & 3);
#pragma unroll
            for (int nt = 0; nt < NT; ++nt) {
                int col = nt * 8 + tg * 2;
                float v0 = acc[t][nt][h * 2], v1 = acc[t][nt][h * 2 + 1];
                if (HB) { v0 += bias[col]; v1 += bias[col + 1]; }
                v0 = softplus_f(v0); v1 = softplus_f(v1);
                float h0, l0, h1, l1; bsplit(v0, h0, l0); bsplit(v1, h1, l1);
                Xw[rw + (col >> 1)] = packbf(h0, h1);        // hi block (words 0..31)
                Xw[rw + 32 + (col >> 1)] = packbf(l0, l1);   // lo block (words 32..63)
            }
        }
    __syncwarp();
}

__global__ void __launch_bounds__(128) bond_kernel(
        const float* __restrict__ bonds,
        const int* __restrict__ ia1,
        const int* __restrict__ ia2,
        const float* __restrict__ eb2,
        const float* __restrict__ eb3,
        float* __restrict__ out) {
    extern __shared__ __align__(16) unsigned char smem[];
    const int tid = threadIdx.x, lane = tid & 31;
    const int w = tid >> 5, g = lane >> 2, tg = lane & 3;
    const int base = blockIdx.x * 128, batch = base >> 18;
    uint32_t* Xw = (uint32_t*)(smem + O_X);
    float* sHb = (float*)(smem + O_HB);
    float* sB2 = (float*)(smem + O_B2);
    float* sB3 = (float*)(smem + O_B3);
    int* sIa1 = (int*)(smem + O_IA1);
    int* sIa2 = (int*)(smem + O_IA2);

    {   // stage weight image (35328 B, linear)
        const uint4* s = (const uint4*)g_wimg;
        uint4* d = (uint4*)smem;
        for (int i = tid; i < 2208; i += 128) d[i] = s[i];
    }
    if (tid < 64) { sHb[tid] = g_hb[batch * HID + tid]; sB2[tid] = eb2[tid]; }
    if (tid < 32) sB3[tid] = eb3[tid];
    sIa1[tid] = ia1[base + tid]; sIa2[tid] = ia2[base + tid];

    {   // stage X0 (row = tid): hi words 0..15, lo words 16..31
        const float4* br = (const float4*)(bonds + (size_t)(base + tid) * FDIM);
        int rw = tid * XW + ((tid >> 3) & 3);
#pragma unroll
        for (int c = 0; c < 8; ++c) {
            float4 v = br[c];
            float h0, l0, h1, l1, h2, l2, h3, l3;
            bsplit(v.x, h0, l0); bsplit(v.y, h1, l1); bsplit(v.z, h2, l2); bsplit(v.w, h3, l3);
            Xw[rw + c * 2] = packbf(h0, h1);      Xw[rw + c * 2 + 1] = packbf(h2, h3);
            Xw[rw + 16 + c * 2] = packbf(l0, l1); Xw[rw + 16 + c * 2 + 1] = packbf(l2, l3);
        }
    }
    __syncthreads();

    // ---- layer 1: acc init = AP1[a1] + AP2[a2] + hb (exact fp32), + bond part via MMA ----
    float acc[2][8][4];
#pragma unroll
    for (int t = 0; t < 2; ++t)
#pragma unroll
        for (int h = 0; h < 2; ++h) {
            int row = w * 32 + t * 16 + h * 8 + g;
            const float2* p1 = (const float2*)(g_AP1 + ((size_t)batch * NA + sIa1[row]) * HID);
            const float2* p2 = (const float2*)(g_AP2 + ((size_t)batch * NA + sIa2[row]) * HID);
#pragma unroll
            for (int nt = 0; nt < 8; ++nt) {
                float2 u = __ldg(p1 + nt * 4 + tg), vv = __ldg(p2 + nt * 4 + tg);
                acc[t][nt][h * 2]     = u.x + vv.x + sHb[nt * 8 + tg * 2];
                acc[t][nt][h * 2 + 1] = u.y + vv.y + sHb[nt * 8 + tg * 2 + 1];
            }
        }
    {
        const int2 S1[6] = {{0,0},{16,16},{32,0},{48,16},{0,32},{16,48}};
        gemm_layer<8, 6>(acc, Xw, smem + O_W1, W1S, S1, w, g, tg);
    }
    epi_store<8, false>(acc, Xw, (const float*)0, w, g, tg);

    // ---- layer 2 ----
#pragma unroll
    for (int t = 0; t < 2; ++t)
#pragma unroll
        for (int nt = 0; nt < 8; ++nt)
#pragma unroll
            for (int q = 0; q < 4; ++q) acc[t][nt][q] = 0.0f;
    {
        const int2 S2[12] = {{0,0},{16,16},{32,32},{48,48},{64,0},{80,16},{96,32},{112,48},
                             {0,64},{16,80},{32,96},{48,112}};
        gemm_layer<8, 12>(acc, Xw, smem + O_W2, W2S, S2, w, g, tg);
    }
    epi_store<8, true>(acc, Xw, sB2, w, g, tg);

    // ---- layer 3 (N=32) ----
    float a3[2][4][4];
#pragma unroll
    for (int t = 0; t < 2; ++t)
#pragma unroll
        for (int nt = 0; nt < 4; ++nt)
#pragma unroll
            for (int q = 0; q < 4; ++q) a3[t][nt][q] = 0.0f;
    {
        const int2 S3[12] = {{0,0},{16,16},{32,32},{48,48},{64,0},{80,16},{96,32},{112,48},
                             {0,64},{16,80},{32,96},{48,112}};
        gemm_layer<4, 12>(a3, Xw, smem + O_W3, W3S, S3, w, g, tg);
    }
    // ---- final epilogue: softplus + out + scatter + bsum ----
    {
        float cs[8];
#pragma unroll
        for (int i = 0; i < 8; ++i) cs[i] = 0.0f;
#pragma unroll
        for (int t = 0; t < 2; ++t)
#pragma unroll
            for (int h = 0; h < 2; ++h) {
                int row = w * 32 + t * 16 + h * 8 + g;
                int ai = sIa1[row];
                float* op = out + (size_t)(base + row) * OUT;
                float* ap = g_accum + ((size_t)batch * NA + ai) * OUT;
#pragma unroll
                for (int nt = 0; nt < 4; ++nt) {
                    int col = nt * 8 + tg * 2;
                    float v0 = softplus_f(a3[t][nt][h * 2] + sB3[col]);
                    float v1 = softplus_f(a3[t][nt][h * 2 + 1] + sB3[col + 1]);
                    *(float2*)(op + col) = make_float2(v0, v1);
                    atomicAdd(ap + col, v0);
                    atomicAdd(ap + col + 1, v1);
                    cs[nt * 2] += v0; cs[nt * 2 + 1] += v1;
                }
                if (tg == 0) atomicAdd(&g_count[batch * NA + ai], 1);
            }
#pragma unroll
        for (int i = 0; i < 8; ++i) {
            float v = cs[i];
            v += __shfl_down_sync(0xffffffffu, v, 16);
            v += __shfl_down_sync(0xffffffffu, v, 8);
            v += __shfl_down_sync(0xffffffffu, v, 4);
            if (lane < 4) atomicAdd(&g_bsum[batch * OUT + (i >> 1) * 8 + tg * 2 + (i & 1)], v);
        }
    }
}

// ---------------- atom MLP (scalar; ~3% of work) ----------------
__global__ void atom_kernel(const float* __restrict__ atoms,
                            const float* __restrict__ state,
                            const float* __restrict__ vw1, const float* __restrict__ vb1,
                            const float* __restrict__ vw2, const float* __restrict__ vb2,
                            const float* __restrict__ vw3, const float* __restrict__ vb3,
                            float* __restrict__ out) {
    extern __shared__ float sm[];
    float* sW1 = sm;
    float* sW2 = sW1 + 96 * HID;
    float* sW3 = sW2 + HID * HID;
    float* scratch = sW3 + HID * OUT;
    float* sB1 = scratch + 128 * 97;
    float* sB2 = sB1 + HID;
    float* sB3 = sB2 + HID;
    float* sMsum = sB3 + OUT;

    int tid = threadIdx.x;
    int a = blockIdx.x * 128 + tid;
    int b = a >> 13;

    for (int i = tid; i < 96 * HID; i += 128) sW1[i] = vw1[i];
    for (int i = tid; i < HID * HID; i += 128) sW2[i] = vw2[i];
    for (int i = tid; i < HID * OUT; i += 128) sW3[i] = vw3[i];
    if (tid < HID) { sB1[tid] = vb1[tid]; sB2[tid] = vb2[tid]; }
    if (tid < OUT) { sB3[tid] = vb3[tid]; sMsum[tid] = 0.0f; }
    __syncthreads();

    float* row = scratch + tid * 97;
    float inv = 1.0f / (float)g_count[a];
    const float4* pa = reinterpret_cast<const float4*>(g_accum + (size_t)a * OUT);
#pragma unroll
    for (int k = 0; k < 8; ++k) {
        float4 v = pa[k];
        row[4*k] = v.x*inv; row[4*k+1] = v.y*inv; row[4*k+2] = v.z*inv; row[4*k+3] = v.w*inv;
    }
    const float4* pt = reinterpret_cast<const float4*>(atoms + (size_t)a * FDIM);
#pragma unroll
    for (int k = 0; k < 8; ++k) {
        float4 v = pt[k];
        row[32+4*k] = v.x; row[32+4*k+1] = v.y; row[32+4*k+2] = v.z; row[32+4*k+3] = v.w;
    }
    const float4* ps = reinterpret_cast<const float4*>(state + (size_t)b * FDIM);
#pragma unroll
    for (int k = 0; k < 8; ++k) {
        float4 v = ps[k];
        row[64+4*k] = v.x; row[64+4*k+1] = v.y; row[64+4*k+2] = v.z; row[64+4*k+3] = v.w;
    }

    float h[HID];
#pragma unroll
    for (int j = 0; j < HID; ++j) h[j] = sB1[j];
    for (int i = 0; i < 96; ++i) {
        float xv = row[i];
        const float4* wr = reinterpret_cast<const float4*>(sW1 + i * HID);
#pragma unroll
        for (int j4 = 0; j4 < 16; ++j4) {
            float4 wv = wr[j4];
            h[4*j4]   = fmaf(xv, wv.x, h[4*j4]);
            h[4*j4+1] = fmaf(xv, wv.y, h[4*j4+1]);
            h[4*j4+2] = fmaf(xv, wv.z, h[4*j4+2]);
            h[4*j4+3] = fmaf(xv, wv.w, h[4*j4+3]);
        }
    }
#pragma unroll
    for (int j = 0; j < HID; ++j) row[j] = softplus_f(h[j]);

    float h2[HID];
#pragma unroll
    for (int j = 0; j < HID; ++j) h2[j] = sB2[j];
    for (int i = 0; i < HID; ++i) {
        float xv = row[i];
        const float4* wr = reinterpret_cast<const float4*>(sW2 + i * HID);
#pragma unroll
        for (int j4 = 0; j4 < 16; ++j4) {
            float4 wv = wr[j4];
            h2[4*j4]   = fmaf(xv, wv.x, h2[4*j4]);
            h2[4*j4+1] = fmaf(xv, wv.y, h2[4*j4+1]);
            h2[4*j4+2] = fmaf(xv, wv.z, h2[4*j4+2]);
            h2[4*j4+3] = fmaf(xv, wv.w, h2[4*j4+3]);
        }
    }
#pragma unroll
    for (int j = 0; j < HID; ++j) row[j] = softplus_f(h2[j]);

    float h3[OUT];
#pragma unroll
    for (int j = 0; j < OUT; ++j) h3[j] = sB3[j];
    for (int i = 0; i < HID; ++i) {
        float xv = row[i];
        const float4* wr = reinterpret_cast<const float4*>(sW3 + i * OUT);
#pragma unroll
        for (int j4 = 0; j4 < 8; ++j4) {
            float4 wv = wr[j4];
            h3[4*j4]   = fmaf(xv, wv.x, h3[4*j4]);
            h3[4*j4+1] = fmaf(xv, wv.y, h3[4*j4+1]);
            h3[4*j4+2] = fmaf(xv, wv.z, h3[4*j4+2]);
            h3[4*j4+3] = fmaf(xv, wv.w, h3[4*j4+3]);
        }
    }
    float o[OUT];
#pragma unroll
    for (int j = 0; j < OUT; ++j) o[j] = softplus_f(h3[j]);

    float4* orow = reinterpret_cast<float4*>(out + (size_t)(BATCH * NB * OUT) + (size_t)a * OUT);
#pragma unroll
    for (int j4 = 0; j4 < 8; ++j4)
        orow[j4] = make_float4(o[4*j4], o[4*j4+1], o[4*j4+2], o[4*j4+3]);

    int lane = tid & 31;
#pragma unroll
    for (int j = 0; j < OUT; ++j) {
        float v = o[j];
        v += __shfl_xor_sync(0xffffffffu, v, 16);
        v += __shfl_xor_sync(0xffffffffu, v, 8);
        v += __shfl_xor_sync(0xffffffffu, v, 4);
        v += __shfl_xor_sync(0xffffffffu, v, 2);
        v += __shfl_xor_sync(0xffffffffu, v, 1);
        if (lane == 0) atomicAdd(&sMsum[j], v);
    }
    __syncthreads();
    if (tid < OUT) atomicAdd(&g_asum[b * OUT + tid], sMsum[tid]);
}

__global__ void state_kernel(const float* __restrict__ state,
                             const float* __restrict__ uw1, const float* __restrict__ ub1,
                             const float* __restrict__ uw2, const float* __restrict__ ub2,
                             const float* __restrict__ uw3, const float* __restrict__ ub3,
                             float* __restrict__ out) {
    __shared__ float uin[96];
    __shared__ float h1s[HID];
    __shared__ float h2s[HID];
    int b = blockIdx.x;
    int j = threadIdx.x;
    if (j < 32) {
        uin[j] = g_bsum[b * OUT + j] * (1.0f / (float)NB);
        uin[32 + j] = g_asum[b * OUT + j] * (1.0f / (float)NA);
        uin[64 + j] = state[b * FDIM + j];
    }
    __syncthreads();
    float acc = ub1[j];
    for (int i = 0; i < 96; ++i) acc = fmaf(uin[i], uw1[i * HID + j], acc);
    h1s[j] = softplus_f(acc);
    __syncthreads();
    acc = ub2[j];
    for (int i = 0; i < HID; ++i) acc = fmaf(h1s[i], uw2[i * HID + j], acc);
    h2s[j] = softplus_f(acc);
    __syncthreads();
    if (j < OUT) {
        acc = ub3[j];
        for (int i = 0; i < HID; ++i) acc = fmaf(h2s[i], uw3[i * OUT + j], acc);
        out[(size_t)(BATCH * NB * OUT) + (size_t)(BATCH * NA * OUT) + b * OUT + j] = softplus_f(acc);
    }
}

extern "C" void kernel_launch(void* const* d_in, const int* in_sizes, int n_in,
                              void* d_out, int out_size) {
    const float* bonds = (const float*)d_in[0];
    const int* ia1 = (const int*)d_in[1];
    const int* ia2 = (const int*)d_in[2];
    const float* atoms = (const float*)d_in[3];
    const float* state = (const float*)d_in[4];
    const float* ew1 = (const float*)d_in[5];
    const float* eb1 = (const float*)d_in[6];
    const float* ew2 = (const float*)d_in[7];
    const float* eb2 = (const float*)d_in[8];
    const float* ew3 = (const float*)d_in[9];
    const float* eb3 = (const float*)d_in[10];
    const float* vw1 = (const float*)d_in[11];
    const float* vb1 = (const float*)d_in[12];
    const float* vw2 = (const float*)d_in[13];
    const float* vb2 = (const float*)d_in[14];
    const float* vw3 = (const float*)d_in[15];
    const float* vb3 = (const float*)d_in[16];
    const float* uw1 = (const float*)d_in[17];
    const float* ub1 = (const float*)d_in[18];
    const float* uw2 = (const float*)d_in[19];
    const float* ub2 = (const float*)d_in[20];
    const float* uw3 = (const float*)d_in[21];
    const float* ub3 = (const float*)d_in[22];
    float* out = (float*)d_out;

    const int AP_SMEM   = (64 * HID + 128 * 33) * (int)sizeof(float);
    const int ATOM_SMEM = (96 * HID + HID * HID + HID * OUT + 128 * 97
                           + HID + HID + OUT + OUT) * (int)sizeof(float);

    cudaFuncSetAttribute(ap_kernel, cudaFuncAttributeMaxDynamicSharedMemorySize, AP_SMEM);
    cudaFuncSetAttribute(bond_kernel, cudaFuncAttributeMaxDynamicSharedMemorySize, BOND_SMEM);
    cudaFuncSetAttribute(atom_kernel, cudaFuncAttributeMaxDynamicSharedMemorySize, ATOM_SMEM);

    zero_kernel<<<1024, 256>>>();
    hb_kernel<<<1, 256>>>(state, ew1, eb1);
    prep_tiles<<<1, 256>>>(ew1, ew2, ew3);
    ap_kernel<<<(BATCH * NA) / 128, 128, AP_SMEM>>>(atoms, ew1);
    bond_kernel<<<(BATCH * NB) / 128, 128, BOND_SMEM>>>(bonds, ia1, ia2, eb2, eb3, out);
    atom_kernel<<<(BATCH * NA) / 128, 128, ATOM_SMEM>>>(atoms, state, vw1, vb1, vw2, vb2, vw3, vb3, out);
    state_kernel<<<BATCH, 64>>>(state, uw1, ub1, uw2, ub2, uw3, ub3, out);
}

// round 9
// speedup vs baseline: 2.7524x; 1.0963x over previous
#include <cuda_runtime.h>
#include <cuda_fp16.h>
#include <cstdint>

#define BATCH 4
#define NB 262144
#define NA 8192
#define FDIM 32
#define HID 64
#define OUT 32

// bond-kernel smem byte offsets (fp16 weight image, 2-pass)
#define O_W1 0
#define O_W2 5120
#define O_W3 14336
#define O_X  18944
#define O_HB 53760
#define O_B2 54016
#define O_B3 54272
#define O_IA1 54400
#define O_IA2 54912
#define BOND_SMEM 55424
#define W1SW 20   // W1 row stride in words (80B) -> conflict-free
#define W2SW 36   // 144B
#define W3SW 36
#define XW 68     // X row stride in words (272B)

__device__ __align__(16) float g_AP1[BATCH * NA * HID];
__device__ __align__(16) float g_AP2[BATCH * NA * HID];
__device__ __align__(16) float g_accum[BATCH * NA * OUT];
__device__ int   g_count[BATCH * NA];
__device__ float g_bsum[BATCH * OUT];
__device__ float g_asum[BATCH * OUT];
__device__ float g_hb[BATCH * HID];
__device__ __align__(16) unsigned char g_wimg[19200]; // fp16 weight image

__device__ __forceinline__ float softplus_f(float x) {
    float e = __expf(-fabsf(x));
    return fmaxf(x, 0.0f) + __logf(1.0f + e);
}
__device__ __forceinline__ void hsplit(float x, float& h, float& l) {
    __half hh = __float2half_rn(x);
    h = __half2float(hh);
    l = x - h;
}
// pack (a -> lo16, b -> hi16) as f16x2
__device__ __forceinline__ uint32_t packh(float a, float b) {
    uint32_t r; asm("cvt.rn.f16x2.f32 %0, %1, %2;" : "=r"(r) : "f"(b), "f"(a)); return r;
}
__device__ __forceinline__ void mma16(float* c, uint32_t a0, uint32_t a1, uint32_t a2, uint32_t a3,
                                      uint32_t b0, uint32_t b1) {
    asm volatile("mma.sync.aligned.m16n8k16.row.col.f32.f16.f16.f32 "
        "{%0,%1,%2,%3}, {%4,%5,%6,%7}, {%8,%9}, {%0,%1,%2,%3};"
        : "+f"(c[0]), "+f"(c[1]), "+f"(c[2]), "+f"(c[3])
        : "r"(a0), "r"(a1), "r"(a2), "r"(a3), "r"(b0), "r"(b1));
}

// ---------------- setup kernels ----------------
__global__ void zero_kernel() {
    int t = blockIdx.x * blockDim.x + threadIdx.x;
    int n = gridDim.x * blockDim.x;
    for (int i = t; i < BATCH * NA * OUT; i += n) g_accum[i] = 0.0f;
    for (int i = t; i < BATCH * NA; i += n) g_count[i] = 0;
    if (t < BATCH * OUT) { g_bsum[t] = 0.0f; g_asum[t] = 0.0f; }
}

__global__ void hb_kernel(const float* __restrict__ state,
                          const float* __restrict__ ew1,
                          const float* __restrict__ eb1) {
    int t = threadIdx.x;
    int b = t >> 6, j = t & 63;
    float acc = eb1[j];
    for (int i = 0; i < FDIM; ++i)
        acc = fmaf(state[b * FDIM + i], ew1[(96 + i) * HID + j], acc);
    g_hb[b * HID + j] = acc;
}

// fp16 weight image: W[n][k] rounded to half
__global__ void prep_tiles(const float* __restrict__ ew1,
                           const float* __restrict__ ew2,
                           const float* __restrict__ ew3) {
    int t = threadIdx.x;
    for (int i = t; i < 64 * 32; i += 256) {     // W1: bond part of e_w1 (rows 64..95)
        int n = i >> 5, k = i & 31;
        *(__half*)(g_wimg + O_W1 + n * 80 + k * 2) = __float2half_rn(ew1[(64 + k) * HID + n]);
    }
    for (int i = t; i < 64 * 64; i += 256) {     // W2
        int n = i >> 6, k = i & 63;
        *(__half*)(g_wimg + O_W2 + n * 144 + k * 2) = __float2half_rn(ew2[k * HID + n]);
    }
    for (int i = t; i < 32 * 64; i += 256) {     // W3
        int n = i >> 6, k = i & 63;
        *(__half*)(g_wimg + O_W3 + n * 144 + k * 2) = __float2half_rn(ew3[k * OUT + n]);
    }
}

// per-atom tables: AP1 = atoms @ e_w1[0:32,:], AP2 = atoms @ e_w1[32:64,:]
__global__ void ap_kernel(const float* __restrict__ atoms,
                          const float* __restrict__ ew1) {
    extern __shared__ float sm[];
    float* sW = sm;
    float* scratch = sm + 64 * HID;
    int tid = threadIdx.x;
    for (int i = tid; i < 64 * HID; i += blockDim.x) sW[i] = ew1[i];
    __syncthreads();
    int a = blockIdx.x * blockDim.x + tid;
    float* row = scratch + tid * 33;
    const float4* arow = reinterpret_cast<const float4*>(atoms + (size_t)a * FDIM);
#pragma unroll
    for (int k = 0; k < 8; ++k) {
        float4 v = arow[k];
        row[4*k] = v.x; row[4*k+1] = v.y; row[4*k+2] = v.z; row[4*k+3] = v.w;
    }
    for (int half = 0; half < 2; ++half) {
        float acc[HID];
#pragma unroll
        for (int j = 0; j < HID; ++j) acc[j] = 0.0f;
        for (int i = 0; i < 32; ++i) {
            float xv = row[i];
            const float4* wr = reinterpret_cast<const float4*>(sW + (half * 32 + i) * HID);
#pragma unroll
            for (int j4 = 0; j4 < 16; ++j4) {
                float4 wv = wr[j4];
                acc[4*j4]   = fmaf(xv, wv.x, acc[4*j4]);
                acc[4*j4+1] = fmaf(xv, wv.y, acc[4*j4+1]);
                acc[4*j4+2] = fmaf(xv, wv.z, acc[4*j4+2]);
                acc[4*j4+3] = fmaf(xv, wv.w, acc[4*j4+3]);
            }
        }
        float4* o = reinterpret_cast<float4*>((half == 0 ? g_AP1 : g_AP2) + (size_t)a * HID);
#pragma unroll
        for (int j4 = 0; j4 < 16; ++j4)
            o[j4] = make_float4(acc[4*j4], acc[4*j4+1], acc[4*j4+2], acc[4*j4+3]);
    }
}

// ---------------- bond MLP: mma.sync fp16 2-pass GEMM ----------------
template<int NT, int NS>
__device__ __forceinline__ void gemm_layer(float (&acc)[2][NT][4], const uint32_t* Xw,
        const uint32_t* Wv, int wsw, const int2* st, int w, int g, int tg) {
#pragma unroll
    for (int s = 0; s < NS; ++s) {
        int ak = st[s].x, bkw = st[s].y;
        uint32_t b0[NT], b1[NT];
#pragma unroll
        for (int nt = 0; nt < NT; ++nt) {
            const uint32_t* bp = Wv + (nt * 8 + g) * wsw + bkw + tg;
            b0[nt] = bp[0]; b1[nt] = bp[4];
        }
#pragma unroll
        for (int t = 0; t < 2; ++t) {
            int r1 = w * 32 + t * 16 + g, r2 = r1 + 8;
            int i1 = r1 * XW + ((r1 >> 3) & 3) + ak + tg;
            int i2 = r2 * XW + ((r2 >> 3) & 3) + ak + tg;
            uint32_t a0 = Xw[i1], a2 = Xw[i1 + 4], a1 = Xw[i2], a3 = Xw[i2 + 4];
#pragma unroll
            for (int nt = 0; nt < NT; ++nt) mma16(acc[t][nt], a0, a1, a2, a3, b0[nt], b1[nt]);
        }
    }
}

template<int NT, bool HB>
__device__ __forceinline__ void epi_store(float (&acc)[2][NT][4], uint32_t* Xw,
        const float* bias, int w, int g, int tg) {
    __syncwarp();
#pragma unroll
    for (int t = 0; t < 2; ++t)
#pragma unroll
        for (int h = 0; h < 2; ++h) {
            int row = w * 32 + t * 16 + h * 8 + g;
            int rw = row * XW + ((row >> 3) & 3);
#pragma unroll
            for (int nt = 0; nt < NT; ++nt) {
                int col = nt * 8 + tg * 2;
                float v0 = acc[t][nt][h * 2], v1 = acc[t][nt][h * 2 + 1];
                if (HB) { v0 += bias[col]; v1 += bias[col + 1]; }
                v0 = softplus_f(v0); v1 = softplus_f(v1);
                float h0, l0, h1, l1; hsplit(v0, h0, l0); hsplit(v1, h1, l1);
                Xw[rw + (col >> 1)] = packh(h0, h1);         // hi block words 0..31
                Xw[rw + 32 + (col >> 1)] = packh(l0, l1);    // lo block words 32..63
            }
        }
    __syncwarp();
}

__global__ void __launch_bounds__(128, 4) bond_kernel(
        const float* __restrict__ bonds,
        const int* __restrict__ ia1,
        const int* __restrict__ ia2,
        const float* __restrict__ eb2,
        const float* __restrict__ eb3,
        float* __restrict__ out) {
    extern __shared__ __align__(16) unsigned char smem[];
    const int tid = threadIdx.x, lane = tid & 31;
    const int w = tid >> 5, g = lane >> 2, tg = lane & 3;
    const int base = blockIdx.x * 128, batch = base >> 18;
    uint32_t* Xw = (uint32_t*)(smem + O_X);
    float* sHb = (float*)(smem + O_HB);
    float* sB2 = (float*)(smem + O_B2);
    float* sB3 = (float*)(smem + O_B3);
    int* sIa1 = (int*)(smem + O_IA1);
    int* sIa2 = (int*)(smem + O_IA2);

    {   // stage fp16 weight image (18944 B, linear)
        const uint4* s = (const uint4*)g_wimg;
        uint4* d = (uint4*)smem;
        for (int i = tid; i < 1184; i += 128) d[i] = s[i];
    }
    if (tid < 64) { sHb[tid] = g_hb[batch * HID + tid]; sB2[tid] = eb2[tid]; }
    if (tid < 32) sB3[tid] = eb3[tid];
    sIa1[tid] = ia1[base + tid]; sIa2[tid] = ia2[base + tid];

    {   // stage X0 (row = tid): hi words 0..15, lo words 16..31
        const float4* br = (const float4*)(bonds + (size_t)(base + tid) * FDIM);
        int rw = tid * XW + ((tid >> 3) & 3);
#pragma unroll
        for (int c = 0; c < 8; ++c) {
            float4 v = br[c];
            float h0, l0, h1, l1, h2, l2, h3, l3;
            hsplit(v.x, h0, l0); hsplit(v.y, h1, l1); hsplit(v.z, h2, l2); hsplit(v.w, h3, l3);
            Xw[rw + c * 2] = packh(h0, h1);      Xw[rw + c * 2 + 1] = packh(h2, h3);
            Xw[rw + 16 + c * 2] = packh(l0, l1); Xw[rw + 16 + c * 2 + 1] = packh(l2, l3);
        }
    }

    // ---- layer-1 acc init = AP1[a1] + AP2[a2] + hb (exact fp32); gathers overlap staging ----
    float acc[2][8][4];
    int mrow_ia1[2][2];
#pragma unroll
    for (int t = 0; t < 2; ++t)
#pragma unroll
        for (int h = 0; h < 2; ++h) {
            int row = w * 32 + t * 16 + h * 8 + g;
            int i1 = __ldg(ia1 + base + row), i2 = __ldg(ia2 + base + row);
            mrow_ia1[t][h] = i1;
            const float2* p1 = (const float2*)(g_AP1 + ((size_t)batch * NA + i1) * HID);
            const float2* p2 = (const float2*)(g_AP2 + ((size_t)batch * NA + i2) * HID);
#pragma unroll
            for (int nt = 0; nt < 8; ++nt) {
                float2 u = __ldg(p1 + nt * 4 + tg), vv = __ldg(p2 + nt * 4 + tg);
                acc[t][nt][h * 2]     = u.x + vv.x + g_hb[batch * HID + nt * 8 + tg * 2];
                acc[t][nt][h * 2 + 1] = u.y + vv.y + g_hb[batch * HID + nt * 8 + tg * 2 + 1];
            }
        }
    __syncthreads();

    // ---- layer 1 (K=32: Ah 2 steps + Al 2 steps) ----
    {
        const int2 S1[4] = {{0,0},{8,8},{16,0},{24,8}};
        gemm_layer<8, 4>(acc, Xw, (const uint32_t*)(smem + O_W1), W1SW, S1, w, g, tg);
    }
    epi_store<8, false>(acc, Xw, (const float*)0, w, g, tg);

    // ---- layer 2 (K=64: 4 hi + 4 lo steps) ----
#pragma unroll
    for (int t = 0; t < 2; ++t)
#pragma unroll
        for (int nt = 0; nt < 8; ++nt)
#pragma unroll
            for (int q = 0; q < 4; ++q) acc[t][nt][q] = 0.0f;
    {
        const int2 S2[8] = {{0,0},{8,8},{16,16},{24,24},{32,0},{40,8},{48,16},{56,24}};
        gemm_layer<8, 8>(acc, Xw, (const uint32_t*)(smem + O_W2), W2SW, S2, w, g, tg);
    }
    epi_store<8, true>(acc, Xw, sB2, w, g, tg);

    // ---- layer 3 (N=32) ----
    float a3[2][4][4];
#pragma unroll
    for (int t = 0; t < 2; ++t)
#pragma unroll
        for (int nt = 0; nt < 4; ++nt)
#pragma unroll
            for (int q = 0; q < 4; ++q) a3[t][nt][q] = 0.0f;
    {
        const int2 S3[8] = {{0,0},{8,8},{16,16},{24,24},{32,0},{40,8},{48,16},{56,24}};
        gemm_layer<4, 8>(a3, Xw, (const uint32_t*)(smem + O_W3), W3SW, S3, w, g, tg);
    }
    // ---- final epilogue: softplus + out + scatter + bsum ----
    {
        float cs[8];
#pragma unroll
        for (int i = 0; i < 8; ++i) cs[i] = 0.0f;
#pragma unroll
        for (int t = 0; t < 2; ++t)
#pragma unroll
            for (int h = 0; h < 2; ++h) {
                int row = w * 32 + t * 16 + h * 8 + g;
                int ai = mrow_ia1[t][h];
                float* op = out + (size_t)(base + row) * OUT;
                float* ap = g_accum + ((size_t)batch * NA + ai) * OUT;
#pragma unroll
                for (int nt = 0; nt < 4; ++nt) {
                    int col = nt * 8 + tg * 2;
                    float v0 = softplus_f(a3[t][nt][h * 2] + sB3[col]);
                    float v1 = softplus_f(a3[t][nt][h * 2 + 1] + sB3[col + 1]);
                    *(float2*)(op + col) = make_float2(v0, v1);
                    atomicAdd(ap + col, v0);
                    atomicAdd(ap + col + 1, v1);
                    cs[nt * 2] += v0; cs[nt * 2 + 1] += v1;
                }
                if (tg == 0) atomicAdd(&g_count[batch * NA + ai], 1);
            }
#pragma unroll
        for (int i = 0; i < 8; ++i) {
            float v = cs[i];
            v += __shfl_down_sync(0xffffffffu, v, 16);
            v += __shfl_down_sync(0xffffffffu, v, 8);
            v += __shfl_down_sync(0xffffffffu, v, 4);
            if (lane < 4) atomicAdd(&g_bsum[batch * OUT + (i >> 1) * 8 + tg * 2 + (i & 1)], v);
        }
    }
    (void)sIa1; (void)sIa2;
}

// ---------------- atom MLP (scalar; ~3% of work) ----------------
__global__ void atom_kernel(const float* __restrict__ atoms,
                            const float* __restrict__ state,
                            const float* __restrict__ vw1, const float* __restrict__ vb1,
                            const float* __restrict__ vw2, const float* __restrict__ vb2,
                            const float* __restrict__ vw3, const float* __restrict__ vb3,
                            float* __restrict__ out) {
    extern __shared__ float sm[];
    float* sW1 = sm;
    float* sW2 = sW1 + 96 * HID;
    float* sW3 = sW2 + HID * HID;
    float* scratch = sW3 + HID * OUT;
    float* sB1 = scratch + 128 * 97;
    float* sB2 = sB1 + HID;
    float* sB3 = sB2 + HID;
    float* sMsum = sB3 + OUT;

    int tid = threadIdx.x;
    int a = blockIdx.x * 128 + tid;
    int b = a >> 13;

    for (int i = tid; i < 96 * HID; i += 128) sW1[i] = vw1[i];
    for (int i = tid; i < HID * HID; i += 128) sW2[i] = vw2[i];
    for (int i = tid; i < HID * OUT; i += 128) sW3[i] = vw3[i];
    if (tid < HID) { sB1[tid] = vb1[tid]; sB2[tid] = vb2[tid]; }
    if (tid < OUT) { sB3[tid] = vb3[tid]; sMsum[tid] = 0.0f; }
    __syncthreads();

    float* row = scratch + tid * 97;
    float inv = 1.0f / (float)g_count[a];
    const float4* pa = reinterpret_cast<const float4*>(g_accum + (size_t)a * OUT);
#pragma unroll
    for (int k = 0; k < 8; ++k) {
        float4 v = pa[k];
        row[4*k] = v.x*inv; row[4*k+1] = v.y*inv; row[4*k+2] = v.z*inv; row[4*k+3] = v.w*inv;
    }
    const float4* pt = reinterpret_cast<const float4*>(atoms + (size_t)a * FDIM);
#pragma unroll
    for (int k = 0; k < 8; ++k) {
        float4 v = pt[k];
        row[32+4*k] = v.x; row[32+4*k+1] = v.y; row[32+4*k+2] = v.z; row[32+4*k+3] = v.w;
    }
    const float4* ps = reinterpret_cast<const float4*>(state + (size_t)b * FDIM);
#pragma unroll
    for (int k = 0; k < 8; ++k) {
        float4 v = ps[k];
        row[64+4*k] = v.x; row[64+4*k+1] = v.y; row[64+4*k+2] = v.z; row[64+4*k+3] = v.w;
    }

    float h[HID];
#pragma unroll
    for (int j = 0; j < HID; ++j) h[j] = sB1[j];
    for (int i = 0; i < 96; ++i) {
        float xv = row[i];
        const float4* wr = reinterpret_cast<const float4*>(sW1 + i * HID);
#pragma unroll
        for (int j4 = 0; j4 < 16; ++j4) {
            float4 wv = wr[j4];
            h[4*j4]   = fmaf(xv, wv.x, h[4*j4]);
            h[4*j4+1] = fmaf(xv, wv.y, h[4*j4+1]);
            h[4*j4+2] = fmaf(xv, wv.z, h[4*j4+2]);
            h[4*j4+3] = fmaf(xv, wv.w, h[4*j4+3]);
        }
    }
#pragma unroll
    for (int j = 0; j < HID; ++j) row[j] = softplus_f(h[j]);

    float h2[HID];
#pragma unroll
    for (int j = 0; j < HID; ++j) h2[j] = sB2[j];
    for (int i = 0; i < HID; ++i) {
        float xv = row[i];
        const float4* wr = reinterpret_cast<const float4*>(sW2 + i * HID);
#pragma unroll
        for (int j4 = 0; j4 < 16; ++j4) {
            float4 wv = wr[j4];
            h2[4*j4]   = fmaf(xv, wv.x, h2[4*j4]);
            h2[4*j4+1] = fmaf(xv, wv.y, h2[4*j4+1]);
            h2[4*j4+2] = fmaf(xv, wv.z, h2[4*j4+2]);
            h2[4*j4+3] = fmaf(xv, wv.w, h2[4*j4+3]);
        }
    }
#pragma unroll
    for (int j = 0; j < HID; ++j) row[j] = softplus_f(h2[j]);

    float h3[OUT];
#pragma unroll
    for (int j = 0; j < OUT; ++j) h3[j] = sB3[j];
    for (int i = 0; i < HID; ++i) {
        float xv = row[i];
        const float4* wr = reinterpret_cast<const float4*>(sW3 + i * OUT);
#pragma unroll
        for (int j4 = 0; j4 < 8; ++j4) {
            float4 wv = wr[j4];
            h3[4*j4]   = fmaf(xv, wv.x, h3[4*j4]);
            h3[4*j4+1] = fmaf(xv, wv.y, h3[4*j4+1]);
            h3[4*j4+2] = fmaf(xv, wv.z, h3[4*j4+2]);
            h3[4*j4+3] = fmaf(xv, wv.w, h3[4*j4+3]);
        }
    }
    float o[OUT];
#pragma unroll
    for (int j = 0; j < OUT; ++j) o[j] = softplus_f(h3[j]);

    float4* orow = reinterpret_cast<float4*>(out + (size_t)(BATCH * NB * OUT) + (size_t)a * OUT);
#pragma unroll
    for (int j4 = 0; j4 < 8; ++j4)
        orow[j4] = make_float4(o[4*j4], o[4*j4+1], o[4*j4+2], o[4*j4+3]);

    int lane = tid & 31;
#pragma unroll
    for (int j = 0; j < OUT; ++j) {
        float v = o[j];
        v += __shfl_xor_sync(0xffffffffu, v, 16);
        v += __shfl_xor_sync(0xffffffffu, v, 8);
        v += __shfl_xor_sync(0xffffffffu, v, 4);
        v += __shfl_xor_sync(0xffffffffu, v, 2);
        v += __shfl_xor_sync(0xffffffffu, v, 1);
        if (lane == 0) atomicAdd(&sMsum[j], v);
    }
    __syncthreads();
    if (tid < OUT) atomicAdd(&g_asum[b * OUT + tid], sMsum[tid]);
}

__global__ void state_kernel(const float* __restrict__ state,
                             const float* __restrict__ uw1, const float* __restrict__ ub1,
                             const float* __restrict__ uw2, const float* __restrict__ ub2,
                             const float* __restrict__ uw3, const float* __restrict__ ub3,
                             float* __restrict__ out) {
    __shared__ float uin[96];
    __shared__ float h1s[HID];
    __shared__ float h2s[HID];
    int b = blockIdx.x;
    int j = threadIdx.x;
    if (j < 32) {
        uin[j] = g_bsum[b * OUT + j] * (1.0f / (float)NB);
        uin[32 + j] = g_asum[b * OUT + j] * (1.0f / (float)NA);
        uin[64 + j] = state[b * FDIM + j];
    }
    __syncthreads();
    float acc = ub1[j];
    for (int i = 0; i < 96; ++i) acc = fmaf(uin[i], uw1[i * HID + j], acc);
    h1s[j] = softplus_f(acc);
    __syncthreads();
    acc = ub2[j];
    for (int i = 0; i < HID; ++i) acc = fmaf(h1s[i], uw2[i * HID + j], acc);
    h2s[j] = softplus_f(acc);
    __syncthreads();
    if (j < OUT) {
        acc = ub3[j];
        for (int i = 0; i < HID; ++i) acc = fmaf(h2s[i], uw3[i * OUT + j], acc);
        out[(size_t)(BATCH * NB * OUT) + (size_t)(BATCH * NA * OUT) + b * OUT + j] = softplus_f(acc);
    }
}

extern "C" void kernel_launch(void* const* d_in, const int* in_sizes, int n_in,
                              void* d_out, int out_size) {
    const float* bonds = (const float*)d_in[0];
    const int* ia1 = (const int*)d_in[1];
    const int* ia2 = (const int*)d_in[2];
    const float* atoms = (const float*)d_in[3];
    const float* state = (const float*)d_in[4];
    const float* ew1 = (const float*)d_in[5];
    const float* eb1 = (const float*)d_in[6];
    const float* ew2 = (const float*)d_in[7];
    const float* eb2 = (const float*)d_in[8];
    const float* ew3 = (const float*)d_in[9];
    const float* eb3 = (const float*)d_in[10];
    const float* vw1 = (const float*)d_in[11];
    const float* vb1 = (const float*)d_in[12];
    const float* vw2 = (const float*)d_in[13];
    const float* vb2 = (const float*)d_in[14];
    const float* vw3 = (const float*)d_in[15];
    const float* vb3 = (const float*)d_in[16];
    const float* uw1 = (const float*)d_in[17];
    const float* ub1 = (const float*)d_in[18];
    const float* uw2 = (const float*)d_in[19];
    const float* ub2 = (const float*)d_in[20];
    const float* uw3 = (const float*)d_in[21];
    const float* ub3 = (const float*)d_in[22];
    float* out = (float*)d_out;

    const int AP_SMEM   = (64 * HID + 128 * 33) * (int)sizeof(float);
    const int ATOM_SMEM = (96 * HID + HID * HID + HID * OUT + 128 * 97
                           + HID + HID + OUT + OUT) * (int)sizeof(float);

    cudaFuncSetAttribute(ap_kernel, cudaFuncAttributeMaxDynamicSharedMemorySize, AP_SMEM);
    cudaFuncSetAttribute(bond_kernel, cudaFuncAttributeMaxDynamicSharedMemorySize, BOND_SMEM);
    cudaFuncSetAttribute(atom_kernel, cudaFuncAttributeMaxDynamicSharedMemorySize, ATOM_SMEM);

    zero_kernel<<<1024, 256>>>();
    hb_kernel<<<1, 256>>>(state, ew1, eb1);
    prep_tiles<<<1, 256>>>(ew1, ew2, ew3);
    ap_kernel<<<(BATCH * NA) / 128, 128, AP_SMEM>>>(atoms, ew1);
    bond_kernel<<<(BATCH * NB) / 128, 128, BOND_SMEM>>>(bonds, ia1, ia2, eb2, eb3, out);
    atom_kernel<<<(BATCH * NA) / 128, 128, ATOM_SMEM>>>(atoms, state, vw1, vb1, vw2, vb2, vw3, vb3, out);
    state_kernel<<<BATCH, 64>>>(state, uw1, ub1, uw2, ub2, uw3, ub3, out);
}

// round 10
// speedup vs baseline: 3.0666x; 1.1141x over previous
#include <cuda_runtime.h>
#include <cuda_fp16.h>
#include <cstdint>

#define BATCH 4
#define NB 262144
#define NA 8192
#define FDIM 32
#define HID 64
#define OUT 32

// bond-kernel smem byte offsets (fp16, single-pass)
#define O_W1 0
#define O_W2 5120
#define O_W3 14336
#define O_X  18944
#define O_B2 37376
#define O_B3 37632
#define BOND_SMEM 37888
#define W1SW 20   // W1 row stride in words (80B)
#define W2SW 36   // 144B
#define W3SW 36
#define XW 36     // X row stride in words (144B; 36 mod 32 = 4 -> conflict-free frags)

__device__ __align__(16) float g_AP1[BATCH * NA * HID];
__device__ __align__(16) float g_AP2[BATCH * NA * HID];
__device__ __align__(16) float g_accum[BATCH * NA * OUT];
__device__ int   g_count[BATCH * NA];
__device__ float g_bsum[BATCH * OUT];
__device__ float g_asum[BATCH * OUT];
__device__ float g_hb[BATCH * HID];
__device__ __align__(16) unsigned char g_wimg[19200]; // fp16 weight image
__device__ int g_sink;

__device__ __forceinline__ float softplus_f(float x) {
    float e = __expf(-fabsf(x));
    return fmaxf(x, 0.0f) + __logf(1.0f + e);
}
// pack (a -> lo16, b -> hi16) as f16x2 (round-to-nearest)
__device__ __forceinline__ uint32_t packh(float a, float b) {
    uint32_t r; asm("cvt.rn.f16x2.f32 %0, %1, %2;" : "=r"(r) : "f"(b), "f"(a)); return r;
}
__device__ __forceinline__ void mma16(float* c, uint32_t a0, uint32_t a1, uint32_t a2, uint32_t a3,
                                      uint32_t b0, uint32_t b1) {
    asm volatile("mma.sync.aligned.m16n8k16.row.col.f32.f16.f16.f32 "
        "{%0,%1,%2,%3}, {%4,%5,%6,%7}, {%8,%9}, {%0,%1,%2,%3};"
        : "+f"(c[0]), "+f"(c[1]), "+f"(c[2]), "+f"(c[3])
        : "r"(a0), "r"(a1), "r"(a2), "r"(a3), "r"(b0), "r"(b1));
}

// ---------------- launch 0: hb + fp16 weight image + small zeros ----------------
__global__ void hbprep_kernel(const float* __restrict__ state,
                              const float* __restrict__ ew1,
                              const float* __restrict__ eb1,
                              const float* __restrict__ ew2,
                              const float* __restrict__ ew3) {
    int t = threadIdx.x;   // 256
    {
        int b = t >> 6, j = t & 63;
        float acc = eb1[j];
        for (int i = 0; i < FDIM; ++i)
            acc = fmaf(state[b * FDIM + i], ew1[(96 + i) * HID + j], acc);
        g_hb[b * HID + j] = acc;
    }
    if (t < BATCH * OUT) { g_bsum[t] = 0.0f; g_asum[t] = 0.0f; }
    for (int i = t; i < 64 * 32; i += 256) {     // W1: bond rows 64..95 of e_w1
        int n = i >> 5, k = i & 31;
        *(__half*)(g_wimg + O_W1 + n * 80 + k * 2) = __float2half_rn(ew1[(64 + k) * HID + n]);
    }
    for (int i = t; i < 64 * 64; i += 256) {     // W2
        int n = i >> 6, k = i & 63;
        *(__half*)(g_wimg + O_W2 + n * 144 + k * 2) = __float2half_rn(ew2[k * HID + n]);
    }
    for (int i = t; i < 32 * 64; i += 256) {     // W3
        int n = i >> 6, k = i & 63;
        *(__half*)(g_wimg + O_W3 + n * 144 + k * 2) = __float2half_rn(ew3[k * OUT + n]);
    }
}

// ---------------- launch 1: AP tables + zero accum/count ----------------
__global__ void ap_kernel(const float* __restrict__ atoms,
                          const float* __restrict__ ew1) {
    extern __shared__ float sm[];
    float* sW = sm;
    float* scratch = sm + 64 * HID;
    int tid = threadIdx.x;
    int gt = blockIdx.x * blockDim.x + tid;     // 32768 threads total
    {   // fold in zeroing of scatter buffers
        float4 z4 = make_float4(0.f, 0.f, 0.f, 0.f);
        float4* za = (float4*)(g_accum) + gt * 8;
#pragma unroll
        for (int i = 0; i < 8; ++i) za[i] = z4;
        g_count[gt] = 0;
    }
    for (int i = tid; i < 64 * HID; i += blockDim.x) sW[i] = ew1[i];
    __syncthreads();
    int a = gt;
    float* row = scratch + tid * 33;
    const float4* arow = reinterpret_cast<const float4*>(atoms + (size_t)a * FDIM);
#pragma unroll
    for (int k = 0; k < 8; ++k) {
        float4 v = arow[k];
        row[4*k] = v.x; row[4*k+1] = v.y; row[4*k+2] = v.z; row[4*k+3] = v.w;
    }
    for (int half = 0; half < 2; ++half) {
        float acc[HID];
#pragma unroll
        for (int j = 0; j < HID; ++j) acc[j] = 0.0f;
        for (int i = 0; i < 32; ++i) {
            float xv = row[i];
            const float4* wr = reinterpret_cast<const float4*>(sW + (half * 32 + i) * HID);
#pragma unroll
            for (int j4 = 0; j4 < 16; ++j4) {
                float4 wv = wr[j4];
                acc[4*j4]   = fmaf(xv, wv.x, acc[4*j4]);
                acc[4*j4+1] = fmaf(xv, wv.y, acc[4*j4+1]);
                acc[4*j4+2] = fmaf(xv, wv.z, acc[4*j4+2]);
                acc[4*j4+3] = fmaf(xv, wv.w, acc[4*j4+3]);
            }
        }
        float4* o = reinterpret_cast<float4*>((half == 0 ? g_AP1 : g_AP2) + (size_t)a * HID);
#pragma unroll
        for (int j4 = 0; j4 < 16; ++j4)
            o[j4] = make_float4(acc[4*j4], acc[4*j4+1], acc[4*j4+2], acc[4*j4+3]);
    }
}

// ---------------- launch 2: separator (aligns ncu capture window onto bond) ----------------
__global__ void sep_kernel() { if (threadIdx.x == 1234) g_sink = 1; }

// ---------------- bond MLP: mma.sync fp16 single-pass GEMM ----------------
template<int NT, int NS>
__device__ __forceinline__ void gemm_layer(float (&acc)[2][NT][4], const uint32_t* Xw,
        const uint32_t* Wv, int wsw, const int2* st, int w, int g, int tg) {
#pragma unroll
    for (int s = 0; s < NS; ++s) {
        int ak = st[s].x, bkw = st[s].y;
        uint32_t b0[NT], b1[NT];
#pragma unroll
        for (int nt = 0; nt < NT; ++nt) {
            const uint32_t* bp = Wv + (nt * 8 + g) * wsw + bkw + tg;
            b0[nt] = bp[0]; b1[nt] = bp[4];
        }
#pragma unroll
        for (int t = 0; t < 2; ++t) {
            int r1 = w * 32 + t * 16 + g, r2 = r1 + 8;
            int i1 = r1 * XW + ((r1 >> 3) & 3) + ak + tg;
            int i2 = r2 * XW + ((r2 >> 3) & 3) + ak + tg;
            uint32_t a0 = Xw[i1], a2 = Xw[i1 + 4], a1 = Xw[i2], a3 = Xw[i2 + 4];
#pragma unroll
            for (int nt = 0; nt < NT; ++nt) mma16(acc[t][nt], a0, a1, a2, a3, b0[nt], b1[nt]);
        }
    }
}

template<int NT, bool HB>
__device__ __forceinline__ void epi_store(float (&acc)[2][NT][4], uint32_t* Xw,
        const float* bias, int w, int g, int tg) {
    __syncwarp();
#pragma unroll
    for (int t = 0; t < 2; ++t)
#pragma unroll
        for (int h = 0; h < 2; ++h) {
            int row = w * 32 + t * 16 + h * 8 + g;
            int rw = row * XW + ((row >> 3) & 3);
#pragma unroll
            for (int nt = 0; nt < NT; ++nt) {
                int col = nt * 8 + tg * 2;
                float v0 = acc[t][nt][h * 2], v1 = acc[t][nt][h * 2 + 1];
                if (HB) { v0 += bias[col]; v1 += bias[col + 1]; }
                v0 = softplus_f(v0); v1 = softplus_f(v1);
                Xw[rw + (col >> 1)] = packh(v0, v1);
            }
        }
    __syncwarp();
}

__global__ void __launch_bounds__(128, 5) bond_kernel(
        const float* __restrict__ bonds,
        const int* __restrict__ ia1,
        const int* __restrict__ ia2,
        const float* __restrict__ eb2,
        const float* __restrict__ eb3,
        float* __restrict__ out) {
    extern __shared__ __align__(16) unsigned char smem[];
    const int tid = threadIdx.x, lane = tid & 31;
    const int w = tid >> 5, g = lane >> 2, tg = lane & 3;
    const int base = blockIdx.x * 128, batch = base >> 18;
    uint32_t* Xw = (uint32_t*)(smem + O_X);
    float* sB2 = (float*)(smem + O_B2);
    float* sB3 = (float*)(smem + O_B3);

    {   // stage fp16 weight image (18944 B, linear)
        const uint4* s = (const uint4*)g_wimg;
        uint4* d = (uint4*)smem;
        for (int i = tid; i < 1184; i += 128) d[i] = s[i];
    }
    if (tid < 64) sB2[tid] = eb2[tid];
    if (tid < 32) sB3[tid] = eb3[tid];

    {   // stage X0 fp16 (row = tid): 16 words
        const float4* br = (const float4*)(bonds + (size_t)(base + tid) * FDIM);
        int rw = tid * XW + ((tid >> 3) & 3);
#pragma unroll
        for (int c = 0; c < 8; ++c) {
            float4 v = br[c];
            Xw[rw + c * 2]     = packh(v.x, v.y);
            Xw[rw + c * 2 + 1] = packh(v.z, v.w);
        }
    }

    // ---- layer-1 acc init = AP1[a1] + AP2[a2] + hb (exact fp32); gathers overlap staging ----
    float acc[2][8][4];
    int mrow_ia1[2][2];
#pragma unroll
    for (int t = 0; t < 2; ++t)
#pragma unroll
        for (int h = 0; h < 2; ++h) {
            int row = w * 32 + t * 16 + h * 8 + g;
            int i1 = __ldg(ia1 + base + row), i2 = __ldg(ia2 + base + row);
            mrow_ia1[t][h] = i1;
            const float2* p1 = (const float2*)(g_AP1 + ((size_t)batch * NA + i1) * HID);
            const float2* p2 = (const float2*)(g_AP2 + ((size_t)batch * NA + i2) * HID);
#pragma unroll
            for (int nt = 0; nt < 8; ++nt) {
                float2 u = __ldg(p1 + nt * 4 + tg), vv = __ldg(p2 + nt * 4 + tg);
                float hb0 = __ldg(g_hb + batch * HID + nt * 8 + tg * 2);
                float hb1 = __ldg(g_hb + batch * HID + nt * 8 + tg * 2 + 1);
                acc[t][nt][h * 2]     = u.x + vv.x + hb0;
                acc[t][nt][h * 2 + 1] = u.y + vv.y + hb1;
            }
        }
    __syncthreads();

    // ---- layer 1 (K=32, 2 steps) ----
    {
        const int2 S1[2] = {{0,0},{8,8}};
        gemm_layer<8, 2>(acc, Xw, (const uint32_t*)(smem + O_W1), W1SW, S1, w, g, tg);
    }
    epi_store<8, false>(acc, Xw, (const float*)0, w, g, tg);

    // ---- layer 2 (K=64, 4 steps) ----
#pragma unroll
    for (int t = 0; t < 2; ++t)
#pragma unroll
        for (int nt = 0; nt < 8; ++nt)
#pragma unroll
            for (int q = 0; q < 4; ++q) acc[t][nt][q] = 0.0f;
    {
        const int2 S2[4] = {{0,0},{8,8},{16,16},{24,24}};
        gemm_layer<8, 4>(acc, Xw, (const uint32_t*)(smem + O_W2), W2SW, S2, w, g, tg);
    }
    epi_store<8, true>(acc, Xw, sB2, w, g, tg);

    // ---- layer 3 (N=32, K=64, 4 steps) ----
    float a3[2][4][4];
#pragma unroll
    for (int t = 0; t < 2; ++t)
#pragma unroll
        for (int nt = 0; nt < 4; ++nt)
#pragma unroll
            for (int q = 0; q < 4; ++q) a3[t][nt][q] = 0.0f;
    {
        const int2 S3[4] = {{0,0},{8,8},{16,16},{24,24}};
        gemm_layer<4, 4>(a3, Xw, (const uint32_t*)(smem + O_W3), W3SW, S3, w, g, tg);
    }
    // ---- final epilogue: softplus + out + scatter + bsum ----
    {
        float cs[8];
#pragma unroll
        for (int i = 0; i < 8; ++i) cs[i] = 0.0f;
#pragma unroll
        for (int t = 0; t < 2; ++t)
#pragma unroll
            for (int h = 0; h < 2; ++h) {
                int row = w * 32 + t * 16 + h * 8 + g;
                int ai = mrow_ia1[t][h];
                float* op = out + (size_t)(base + row) * OUT;
                float* ap = g_accum + ((size_t)batch * NA + ai) * OUT;
#pragma unroll
                for (int nt = 0; nt < 4; ++nt) {
                    int col = nt * 8 + tg * 2;
                    float v0 = softplus_f(a3[t][nt][h * 2] + sB3[col]);
                    float v1 = softplus_f(a3[t][nt][h * 2 + 1] + sB3[col + 1]);
                    *(float2*)(op + col) = make_float2(v0, v1);
                    atomicAdd(ap + col, v0);
                    atomicAdd(ap + col + 1, v1);
                    cs[nt * 2] += v0; cs[nt * 2 + 1] += v1;
                }
                if (tg == 0) atomicAdd(&g_count[batch * NA + ai], 1);
            }
#pragma unroll
        for (int i = 0; i < 8; ++i) {
            float v = cs[i];
            v += __shfl_down_sync(0xffffffffu, v, 16);
            v += __shfl_down_sync(0xffffffffu, v, 8);
            v += __shfl_down_sync(0xffffffffu, v, 4);
            if (lane < 4) atomicAdd(&g_bsum[batch * OUT + (i >> 1) * 8 + tg * 2 + (i & 1)], v);
        }
    }
}

// ---------------- atom MLP (scalar; ~3% of work) ----------------
__global__ void atom_kernel(const float* __restrict__ atoms,
                            const float* __restrict__ state,
                            const float* __restrict__ vw1, const float* __restrict__ vb1,
                            const float* __restrict__ vw2, const float* __restrict__ vb2,
                            const float* __restrict__ vw3, const float* __restrict__ vb3,
                            float* __restrict__ out) {
    extern __shared__ float sm[];
    float* sW1 = sm;
    float* sW2 = sW1 + 96 * HID;
    float* sW3 = sW2 + HID * HID;
    float* scratch = sW3 + HID * OUT;
    float* sB1 = scratch + 128 * 97;
    float* sB2 = sB1 + HID;
    float* sB3 = sB2 + HID;
    float* sMsum = sB3 + OUT;

    int tid = threadIdx.x;
    int a = blockIdx.x * 128 + tid;
    int b = a >> 13;

    for (int i = tid; i < 96 * HID; i += 128) sW1[i] = vw1[i];
    for (int i = tid; i < HID * HID; i += 128) sW2[i] = vw2[i];
    for (int i = tid; i < HID * OUT; i += 128) sW3[i] = vw3[i];
    if (tid < HID) { sB1[tid] = vb1[tid]; sB2[tid] = vb2[tid]; }
    if (tid < OUT) { sB3[tid] = vb3[tid]; sMsum[tid] = 0.0f; }
    __syncthreads();

    float* row = scratch + tid * 97;
    float inv = 1.0f / (float)g_count[a];
    const float4* pa = reinterpret_cast<const float4*>(g_accum + (size_t)a * OUT);
#pragma unroll
    for (int k = 0; k < 8; ++k) {
        float4 v = pa[k];
        row[4*k] = v.x*inv; row[4*k+1] = v.y*inv; row[4*k+2] = v.z*inv; row[4*k+3] = v.w*inv;
    }
    const float4* pt = reinterpret_cast<const float4*>(atoms + (size_t)a * FDIM);
#pragma unroll
    for (int k = 0; k < 8; ++k) {
        float4 v = pt[k];
        row[32+4*k] = v.x; row[32+4*k+1] = v.y; row[32+4*k+2] = v.z; row[32+4*k+3] = v.w;
    }
    const float4* ps = reinterpret_cast<const float4*>(state + (size_t)b * FDIM);
#pragma unroll
    for (int k = 0; k < 8; ++k) {
        float4 v = ps[k];
        row[64+4*k] = v.x; row[64+4*k+1] = v.y; row[64+4*k+2] = v.z; row[64+4*k+3] = v.w;
    }

    float h[HID];
#pragma unroll
    for (int j = 0; j < HID; ++j) h[j] = sB1[j];
    for (int i = 0; i < 96; ++i) {
        float xv = row[i];
        const float4* wr = reinterpret_cast<const float4*>(sW1 + i * HID);
#pragma unroll
        for (int j4 = 0; j4 < 16; ++j4) {
            float4 wv = wr[j4];
            h[4*j4]   = fmaf(xv, wv.x, h[4*j4]);
            h[4*j4+1] = fmaf(xv, wv.y, h[4*j4+1]);
            h[4*j4+2] = fmaf(xv, wv.z, h[4*j4+2]);
            h[4*j4+3] = fmaf(xv, wv.w, h[4*j4+3]);
        }
    }
#pragma unroll
    for (int j = 0; j < HID; ++j) row[j] = softplus_f(h[j]);

    float h2[HID];
#pragma unroll
    for (int j = 0; j < HID; ++j) h2[j] = sB2[j];
    for (int i = 0; i < HID; ++i) {
        float xv = row[i];
        const float4* wr = reinterpret_cast<const float4*>(sW2 + i * HID);
#pragma unroll
        for (int j4 = 0; j4 < 16; ++j4) {
            float4 wv = wr[j4];
            h2[4*j4]   = fmaf(xv, wv.x, h2[4*j4]);
            h2[4*j4+1] = fmaf(xv, wv.y, h2[4*j4+1]);
            h2[4*j4+2] = fmaf(xv, wv.z, h2[4*j4+2]);
            h2[4*j4+3] = fmaf(xv, wv.w, h2[4*j4+3]);
        }
    }
#pragma unroll
    for (int j = 0; j < HID; ++j) row[j] = softplus_f(h2[j]);

    float h3[OUT];
#pragma unroll
    for (int j = 0; j < OUT; ++j) h3[j] = sB3[j];
    for (int i = 0; i < HID; ++i) {
        float xv = row[i];
        const float4* wr = reinterpret_cast<const float4*>(sW3 + i * OUT);
#pragma unroll
        for (int j4 = 0; j4 < 8; ++j4) {
            float4 wv = wr[j4];
            h3[4*j4]   = fmaf(xv, wv.x, h3[4*j4]);
            h3[4*j4+1] = fmaf(xv, wv.y, h3[4*j4+1]);
            h3[4*j4+2] = fmaf(xv, wv.z, h3[4*j4+2]);
            h3[4*j4+3] = fmaf(xv, wv.w, h3[4*j4+3]);
        }
    }
    float o[OUT];
#pragma unroll
    for (int j = 0; j < OUT; ++j) o[j] = softplus_f(h3[j]);

    float4* orow = reinterpret_cast<float4*>(out + (size_t)(BATCH * NB * OUT) + (size_t)a * OUT);
#pragma unroll
    for (int j4 = 0; j4 < 8; ++j4)
        orow[j4] = make_float4(o[4*j4], o[4*j4+1], o[4*j4+2], o[4*j4+3]);

    int lane = tid & 31;
#pragma unroll
    for (int j = 0; j < OUT; ++j) {
        float v = o[j];
        v += __shfl_xor_sync(0xffffffffu, v, 16);
        v += __shfl_xor_sync(0xffffffffu, v, 8);
        v += __shfl_xor_sync(0xffffffffu, v, 4);
        v += __shfl_xor_sync(0xffffffffu, v, 2);
        v += __shfl_xor_sync(0xffffffffu, v, 1);
        if (lane == 0) atomicAdd(&sMsum[j], v);
    }
    __syncthreads();
    if (tid < OUT) atomicAdd(&g_asum[b * OUT + tid], sMsum[tid]);
}

__global__ void state_kernel(const float* __restrict__ state,
                             const float* __restrict__ uw1, const float* __restrict__ ub1,
                             const float* __restrict__ uw2, const float* __restrict__ ub2,
                             const float* __restrict__ uw3, const float* __restrict__ ub3,
                             float* __restrict__ out) {
    __shared__ float uin[96];
    __shared__ float h1s[HID];
    __shared__ float h2s[HID];
    int b = blockIdx.x;
    int j = threadIdx.x;
    if (j < 32) {
        uin[j] = g_bsum[b * OUT + j] * (1.0f / (float)NB);
        uin[32 + j] = g_asum[b * OUT + j] * (1.0f / (float)NA);
        uin[64 + j] = state[b * FDIM + j];
    }
    __syncthreads();
    float acc = ub1[j];
    for (int i = 0; i < 96; ++i) acc = fmaf(uin[i], uw1[i * HID + j], acc);
    h1s[j] = softplus_f(acc);
    __syncthreads();
    acc = ub2[j];
    for (int i = 0; i < HID; ++i) acc = fmaf(h1s[i], uw2[i * HID + j], acc);
    h2s[j] = softplus_f(acc);
    __syncthreads();
    if (j < OUT) {
        acc = ub3[j];
        for (int i = 0; i < HID; ++i) acc = fmaf(h2s[i], uw3[i * OUT + j], acc);
        out[(size_t)(BATCH * NB * OUT) + (size_t)(BATCH * NA * OUT) + b * OUT + j] = softplus_f(acc);
    }
}

extern "C" void kernel_launch(void* const* d_in, const int* in_sizes, int n_in,
                              void* d_out, int out_size) {
    const float* bonds = (const float*)d_in[0];
    const int* ia1 = (const int*)d_in[1];
    const int* ia2 = (const int*)d_in[2];
    const float* atoms = (const float*)d_in[3];
    const float* state = (const float*)d_in[4];
    const float* ew1 = (const float*)d_in[5];
    const float* eb1 = (const float*)d_in[6];
    const float* ew2 = (const float*)d_in[7];
    const float* eb2 = (const float*)d_in[8];
    const float* ew3 = (const float*)d_in[9];
    const float* eb3 = (const float*)d_in[10];
    const float* vw1 = (const float*)d_in[11];
    const float* vb1 = (const float*)d_in[12];
    const float* vw2 = (const float*)d_in[13];
    const float* vb2 = (const float*)d_in[14];
    const float* vw3 = (const float*)d_in[15];
    const float* vb3 = (const float*)d_in[16];
    const float* uw1 = (const float*)d_in[17];
    const float* ub1 = (const float*)d_in[18];
    const float* uw2 = (const float*)d_in[19];
    const float* ub2 = (const float*)d_in[20];
    const float* uw3 = (const float*)d_in[21];
    const float* ub3 = (const float*)d_in[22];
    float* out = (float*)d_out;

    const int AP_SMEM   = (64 * HID + 128 * 33) * (int)sizeof(float);
    const int ATOM_SMEM = (96 * HID + HID * HID + HID * OUT + 128 * 97
                           + HID + HID + OUT + OUT) * (int)sizeof(float);

    cudaFuncSetAttribute(ap_kernel, cudaFuncAttributeMaxDynamicSharedMemorySize, AP_SMEM);
    cudaFuncSetAttribute(bond_kernel, cudaFuncAttributeMaxDynamicSharedMemorySize, BOND_SMEM);
    cudaFuncSetAttribute(atom_kernel, cudaFuncAttributeMaxDynamicSharedMemorySize, ATOM_SMEM);

    hbprep_kernel<<<1, 256>>>(state, ew1, eb1, ew2, ew3);                 // 0
    ap_kernel<<<(BATCH * NA) / 128, 128, AP_SMEM>>>(atoms, ew1);          // 1
    sep_kernel<<<1, 32>>>();                                              // 2
    bond_kernel<<<(BATCH * NB) / 128, 128, BOND_SMEM>>>(bonds, ia1, ia2, eb2, eb3, out);  // 3 (ncu target)
    atom_kernel<<<(BATCH * NA) / 128, 128, ATOM_SMEM>>>(atoms, state, vw1, vb1, vw2, vb2, vw3, vb3, out);
    state_kernel<<<BATCH, 64>>>(state, uw1, ub1, uw2, ub2, uw3, ub3, out);
}

// round 12
// speedup vs baseline: 3.6183x; 1.1799x over previous
#include <cuda_runtime.h>
#include <cuda_fp16.h>
#include <cstdint>

#define BATCH 4
#define NB 262144
#define NA 8192
#define FDIM 32
#define HID 64
#define OUT 32

// bond-kernel smem byte offsets (fp16, single-pass)
#define O_W1 0
#define O_W2 5120
#define O_W3 14336
#define O_X  18944
#define O_B2 37376
#define O_B3 37632
#define BOND_SMEM 37888
#define W1SW 20   // W1 row stride in words (80B)
#define W2SW 36   // 144B
#define W3SW 36
#define XW 36     // fp16 X row stride in words (144B)
#define RS 36     // fp32 restage row stride in words (144B); 128*144 = 18432 fits O_X region

__device__ __align__(16) float g_AP1[BATCH * NA * HID];
__device__ __align__(16) float g_AP2[BATCH * NA * HID];
__device__ __align__(16) float g_accum[BATCH * NA * OUT];
__device__ int   g_count[BATCH * NA];
__device__ float g_bsum[BATCH * OUT];
__device__ float g_asum[BATCH * OUT];
__device__ float g_hb[BATCH * HID];
__device__ __align__(16) unsigned char g_wimg[19200]; // fp16 weight image
__device__ int g_sink;

__device__ __forceinline__ float softplus_f(float x) {
    float e = __expf(-fabsf(x));
    return fmaxf(x, 0.0f) + __logf(1.0f + e);
}
__device__ __forceinline__ uint32_t packh(float a, float b) {
    uint32_t r; asm("cvt.rn.f16x2.f32 %0, %1, %2;" : "=r"(r) : "f"(b), "f"(a)); return r;
}
__device__ __forceinline__ void mma16(float* c, uint32_t a0, uint32_t a1, uint32_t a2, uint32_t a3,
                                      uint32_t b0, uint32_t b1) {
    asm volatile("mma.sync.aligned.m16n8k16.row.col.f32.f16.f16.f32 "
        "{%0,%1,%2,%3}, {%4,%5,%6,%7}, {%8,%9}, {%0,%1,%2,%3};"
        : "+f"(c[0]), "+f"(c[1]), "+f"(c[2]), "+f"(c[3])
        : "r"(a0), "r"(a1), "r"(a2), "r"(a3), "r"(b0), "r"(b1));
}
__device__ __forceinline__ void red4(float* p, float a, float b, float c, float d) {
    asm volatile("red.global.add.v4.f32 [%0], {%1,%2,%3,%4};"
                 :: "l"(p), "f"(a), "f"(b), "f"(c), "f"(d) : "memory");
}

// ---------------- launch 0: hb + fp16 weight image + small zeros ----------------
__global__ void hbprep_kernel(const float* __restrict__ state,
                              const float* __restrict__ ew1,
                              const float* __restrict__ eb1,
                              const float* __restrict__ ew2,
                              const float* __restrict__ ew3) {
    int t = threadIdx.x;   // 256
    {
        int b = t >> 6, j = t & 63;
        float acc = eb1[j];
        for (int i = 0; i < FDIM; ++i)
            acc = fmaf(state[b * FDIM + i], ew1[(96 + i) * HID + j], acc);
        g_hb[b * HID + j] = acc;
    }
    if (t < BATCH * OUT) { g_bsum[t] = 0.0f; g_asum[t] = 0.0f; }
    for (int i = t; i < 64 * 32; i += 256) {     // W1: bond rows 64..95 of e_w1
        int n = i >> 5, k = i & 31;
        *(__half*)(g_wimg + O_W1 + n * 80 + k * 2) = __float2half_rn(ew1[(64 + k) * HID + n]);
    }
    for (int i = t; i < 64 * 64; i += 256) {     // W2
        int n = i >> 6, k = i & 63;
        *(__half*)(g_wimg + O_W2 + n * 144 + k * 2) = __float2half_rn(ew2[k * HID + n]);
    }
    for (int i = t; i < 32 * 64; i += 256) {     // W3
        int n = i >> 6, k = i & 63;
        *(__half*)(g_wimg + O_W3 + n * 144 + k * 2) = __float2half_rn(ew3[k * OUT + n]);
    }
}

// ---------------- launch 1: AP tables + zero accum/count ----------------
__global__ void ap_kernel(const float* __restrict__ atoms,
                          const float* __restrict__ ew1) {
    extern __shared__ float sm[];
    float* sW = sm;
    float* scratch = sm + 64 * HID;
    int tid = threadIdx.x;
    int gt = blockIdx.x * blockDim.x + tid;
    {
        float4 z4 = make_float4(0.f, 0.f, 0.f, 0.f);
        float4* za = (float4*)(g_accum) + gt * 8;
#pragma unroll
        for (int i = 0; i < 8; ++i) za[i] = z4;
        g_count[gt] = 0;
    }
    for (int i = tid; i < 64 * HID; i += blockDim.x) sW[i] = ew1[i];
    __syncthreads();
    int a = gt;
    float* row = scratch + tid * 33;
    const float4* arow = reinterpret_cast<const float4*>(atoms + (size_t)a * FDIM);
#pragma unroll
    for (int k = 0; k < 8; ++k) {
        float4 v = arow[k];
        row[4*k] = v.x; row[4*k+1] = v.y; row[4*k+2] = v.z; row[4*k+3] = v.w;
    }
    for (int half = 0; half < 2; ++half) {
        float acc[HID];
#pragma unroll
        for (int j = 0; j < HID; ++j) acc[j] = 0.0f;
        for (int i = 0; i < 32; ++i) {
            float xv = row[i];
            const float4* wr = reinterpret_cast<const float4*>(sW + (half * 32 + i) * HID);
#pragma unroll
            for (int j4 = 0; j4 < 16; ++j4) {
                float4 wv = wr[j4];
                acc[4*j4]   = fmaf(xv, wv.x, acc[4*j4]);
                acc[4*j4+1] = fmaf(xv, wv.y, acc[4*j4+1]);
                acc[4*j4+2] = fmaf(xv, wv.z, acc[4*j4+2]);
                acc[4*j4+3] = fmaf(xv, wv.w, acc[4*j4+3]);
            }
        }
        float4* o = reinterpret_cast<float4*>((half == 0 ? g_AP1 : g_AP2) + (size_t)a * HID);
#pragma unroll
        for (int j4 = 0; j4 < 16; ++j4)
            o[j4] = make_float4(acc[4*j4], acc[4*j4+1], acc[4*j4+2], acc[4*j4+3]);
    }
}

// ---------------- launch 2: separator (aligns ncu capture window onto bond) ----------------
__global__ void sep_kernel() { if (threadIdx.x == 1234) g_sink = 1; }

// ---------------- bond MLP: mma.sync fp16 single-pass GEMM ----------------
template<int NT, int NS>
__device__ __forceinline__ void gemm_layer(float (&acc)[2][NT][4], const uint32_t* Xw,
        const uint32_t* Wv, int wsw, const int2* st, int w, int g, int tg) {
#pragma unroll
    for (int s = 0; s < NS; ++s) {
        int ak = st[s].x, bkw = st[s].y;
        uint32_t b0[NT], b1[NT];
#pragma unroll
        for (int nt = 0; nt < NT; ++nt) {
            const uint32_t* bp = Wv + (nt * 8 + g) * wsw + bkw + tg;
            b0[nt] = bp[0]; b1[nt] = bp[4];
        }
#pragma unroll
        for (int t = 0; t < 2; ++t) {
            int r1 = w * 32 + t * 16 + g, r2 = r1 + 8;
            int i1 = r1 * XW + ((r1 >> 3) & 3) + ak + tg;
            int i2 = r2 * XW + ((r2 >> 3) & 3) + ak + tg;
            uint32_t a0 = Xw[i1], a2 = Xw[i1 + 4], a1 = Xw[i2], a3 = Xw[i2 + 4];
#pragma unroll
            for (int nt = 0; nt < NT; ++nt) mma16(acc[t][nt], a0, a1, a2, a3, b0[nt], b1[nt]);
        }
    }
}

template<int NT, bool HB>
__device__ __forceinline__ void epi_store(float (&acc)[2][NT][4], uint32_t* Xw,
        const float* bias, int w, int g, int tg) {
    __syncwarp();
#pragma unroll
    for (int t = 0; t < 2; ++t)
#pragma unroll
        for (int h = 0; h < 2; ++h) {
            int row = w * 32 + t * 16 + h * 8 + g;
            int rw = row * XW + ((row >> 3) & 3);
#pragma unroll
            for (int nt = 0; nt < NT; ++nt) {
                int col = nt * 8 + tg * 2;
                float v0 = acc[t][nt][h * 2], v1 = acc[t][nt][h * 2 + 1];
                if (HB) { v0 += bias[col]; v1 += bias[col + 1]; }
                v0 = softplus_f(v0); v1 = softplus_f(v1);
                Xw[rw + (col >> 1)] = packh(v0, v1);
            }
        }
    __syncwarp();
}

__global__ void __launch_bounds__(128, 5) bond_kernel(
        const float* __restrict__ bonds,
        const int* __restrict__ ia1,
        const int* __restrict__ ia2,
        const float* __restrict__ eb2,
        const float* __restrict__ eb3,
        float* __restrict__ out) {
    extern __shared__ __align__(16) unsigned char smem[];
    const int tid = threadIdx.x, lane = tid & 31;
    const int w = tid >> 5, g = lane >> 2, tg = lane & 3;
    const int base = blockIdx.x * 128, batch = base >> 18;
    uint32_t* Xw = (uint32_t*)(smem + O_X);
    float* Xf = (float*)(smem + O_X);
    float* sB2 = (float*)(smem + O_B2);
    float* sB3 = (float*)(smem + O_B3);

    {   // stage fp16 weight image (18944 B, linear)
        const uint4* s = (const uint4*)g_wimg;
        uint4* d = (uint4*)smem;
        for (int i = tid; i < 1184; i += 128) d[i] = s[i];
    }
    if (tid < 64) sB2[tid] = eb2[tid];
    if (tid < 32) sB3[tid] = eb3[tid];

    {   // stage X0 fp16 (row = tid): 16 words
        const float4* br = (const float4*)(bonds + (size_t)(base + tid) * FDIM);
        int rw = tid * XW + ((tid >> 3) & 3);
#pragma unroll
        for (int c = 0; c < 8; ++c) {
            float4 v = br[c];
            Xw[rw + c * 2]     = packh(v.x, v.y);
            Xw[rw + c * 2 + 1] = packh(v.z, v.w);
        }
    }

    // ---- layer-1 acc init = AP1[a1] + AP2[a2] + hb (exact fp32); gathers overlap staging ----
    float acc[2][8][4];
#pragma unroll
    for (int t = 0; t < 2; ++t)
#pragma unroll
        for (int h = 0; h < 2; ++h) {
            int row = w * 32 + t * 16 + h * 8 + g;
            int i1 = __ldg(ia1 + base + row), i2 = __ldg(ia2 + base + row);
            const float2* p1 = (const float2*)(g_AP1 + ((size_t)batch * NA + i1) * HID);
            const float2* p2 = (const float2*)(g_AP2 + ((size_t)batch * NA + i2) * HID);
#pragma unroll
            for (int nt = 0; nt < 8; ++nt) {
                float2 u = __ldg(p1 + nt * 4 + tg), vv = __ldg(p2 + nt * 4 + tg);
                float hb0 = __ldg(g_hb + batch * HID + nt * 8 + tg * 2);
                float hb1 = __ldg(g_hb + batch * HID + nt * 8 + tg * 2 + 1);
                acc[t][nt][h * 2]     = u.x + vv.x + hb0;
                acc[t][nt][h * 2 + 1] = u.y + vv.y + hb1;
            }
        }
    __syncthreads();

    // ---- layer 1 (K=32, 2 steps) ----
    {
        const int2 S1[2] = {{0,0},{8,8}};
        gemm_layer<8, 2>(acc, Xw, (const uint32_t*)(smem + O_W1), W1SW, S1, w, g, tg);
    }
    epi_store<8, false>(acc, Xw, (const float*)0, w, g, tg);

    // ---- layer 2 (K=64, 4 steps) ----
#pragma unroll
    for (int t = 0; t < 2; ++t)
#pragma unroll
        for (int nt = 0; nt < 8; ++nt)
#pragma unroll
            for (int q = 0; q < 4; ++q) acc[t][nt][q] = 0.0f;
    {
        const int2 S2[4] = {{0,0},{8,8},{16,16},{24,24}};
        gemm_layer<8, 4>(acc, Xw, (const uint32_t*)(smem + O_W2), W2SW, S2, w, g, tg);
    }
    epi_store<8, true>(acc, Xw, sB2, w, g, tg);

    // ---- layer 3 (N=32, K=64, 4 steps) ----
    float a3[2][4][4];
#pragma unroll
    for (int t = 0; t < 2; ++t)
#pragma unroll
        for (int nt = 0; nt < 4; ++nt)
#pragma unroll
            for (int q = 0; q < 4; ++q) a3[t][nt][q] = 0.0f;
    {
        const int2 S3[4] = {{0,0},{8,8},{16,16},{24,24}};
        gemm_layer<4, 4>(a3, Xw, (const uint32_t*)(smem + O_W3), W3SW, S3, w, g, tg);
    }

    // ---- final epilogue: softplus -> fp32 restage (warp-local) -> coalesced STG + red.v4 ----
    __syncwarp();   // all reads of fp16 X done before overwrite
#pragma unroll
    for (int t = 0; t < 2; ++t)
#pragma unroll
        for (int h = 0; h < 2; ++h) {
            int row = w * 32 + t * 16 + h * 8 + g;
#pragma unroll
            for (int nt = 0; nt < 4; ++nt) {
                int col = nt * 8 + tg * 2;
                float v0 = softplus_f(a3[t][nt][h * 2] + sB3[col]);
                float v1 = softplus_f(a3[t][nt][h * 2 + 1] + sB3[col + 1]);
                *(float2*)(Xf + row * RS + col) = make_float2(v0, v1);
            }
        }
    __syncwarp();
    {
        int cg = lane & 3;              // column group: cols cg*8 .. cg*8+7
        int rsub = lane >> 2;           // row-subindex 0..7
        float cs[8];
#pragma unroll
        for (int i = 0; i < 8; ++i) cs[i] = 0.0f;
#pragma unroll
        for (int it = 0; it < 4; ++it) {
            int row = w * 32 + it * 8 + rsub;
            float4 q0 = *(float4*)(Xf + row * RS + cg * 8);
            float4 q1 = *(float4*)(Xf + row * RS + cg * 8 + 4);
            int ai = __ldg(ia1 + base + row);
            float* op = out + (size_t)(base + row) * OUT + cg * 8;
            *(float4*)op = q0;
            *(float4*)(op + 4) = q1;
            float* ap = g_accum + ((size_t)batch * NA + ai) * OUT + cg * 8;
            red4(ap, q0.x, q0.y, q0.z, q0.w);
            red4(ap + 4, q1.x, q1.y, q1.z, q1.w);
            if (cg == 0) atomicAdd(&g_count[batch * NA + ai], 1);
            cs[0] += q0.x; cs[1] += q0.y; cs[2] += q0.z; cs[3] += q0.w;
            cs[4] += q1.x; cs[5] += q1.y; cs[6] += q1.z; cs[7] += q1.w;
        }
#pragma unroll
        for (int i = 0; i < 8; ++i) {
            cs[i] += __shfl_xor_sync(0xffffffffu, cs[i], 16);
            cs[i] += __shfl_xor_sync(0xffffffffu, cs[i], 8);
            cs[i] += __shfl_xor_sync(0xffffffffu, cs[i], 4);
        }
        if (lane < 4) {
            float* bp = g_bsum + batch * OUT + lane * 8;
            red4(bp, cs[0], cs[1], cs[2], cs[3]);
            red4(bp + 4, cs[4], cs[5], cs[6], cs[7]);
        }
    }
}

// ---------------- atom MLP (scalar; ~3% of work) ----------------
__global__ void atom_kernel(const float* __restrict__ atoms,
                            const float* __restrict__ state,
                            const float* __restrict__ vw1, const float* __restrict__ vb1,
                            const float* __restrict__ vw2, const float* __restrict__ vb2,
                            const float* __restrict__ vw3, const float* __restrict__ vb3,
                            float* __restrict__ out) {
    extern __shared__ float sm[];
    float* sW1 = sm;
    float* sW2 = sW1 + 96 * HID;
    float* sW3 = sW2 + HID * HID;
    float* scratch = sW3 + HID * OUT;
    float* sB1 = scratch + 128 * 97;
    float* sB2 = sB1 + HID;
    float* sB3 = sB2 + HID;
    float* sMsum = sB3 + OUT;

    int tid = threadIdx.x;
    int a = blockIdx.x * 128 + tid;
    int b = a >> 13;

    for (int i = tid; i < 96 * HID; i += 128) sW1[i] = vw1[i];
    for (int i = tid; i < HID * HID; i += 128) sW2[i] = vw2[i];
    for (int i = tid; i < HID * OUT; i += 128) sW3[i] = vw3[i];
    if (tid < HID) { sB1[tid] = vb1[tid]; sB2[tid] = vb2[tid]; }
    if (tid < OUT) { sB3[tid] = vb3[tid]; sMsum[tid] = 0.0f; }
    __syncthreads();

    float* row = scratch + tid * 97;
    float inv = 1.0f / (float)g_count[a];
    const float4* pa = reinterpret_cast<const float4*>(g_accum + (size_t)a * OUT);
#pragma unroll
    for (int k = 0; k < 8; ++k) {
        float4 v = pa[k];
        row[4*k] = v.x*inv; row[4*k+1] = v.y*inv; row[4*k+2] = v.z*inv; row[4*k+3] = v.w*inv;
    }
    const float4* pt = reinterpret_cast<const float4*>(atoms + (size_t)a * FDIM);
#pragma unroll
    for (int k = 0; k < 8; ++k) {
        float4 v = pt[k];
        row[32+4*k] = v.x; row[32+4*k+1] = v.y; row[32+4*k+2] = v.z; row[32+4*k+3] = v.w;
    }
    const float4* ps = reinterpret_cast<const float4*>(state + (size_t)b * FDIM);
#pragma unroll
    for (int k = 0; k < 8; ++k) {
        float4 v = ps[k];
        row[64+4*k] = v.x; row[64+4*k+1] = v.y; row[64+4*k+2] = v.z; row[64+4*k+3] = v.w;
    }

    float h[HID];
#pragma unroll
    for (int j = 0; j < HID; ++j) h[j] = sB1[j];
    for (int i = 0; i < 96; ++i) {
        float xv = row[i];
        const float4* wr = reinterpret_cast<const float4*>(sW1 + i * HID);
#pragma unroll
        for (int j4 = 0; j4 < 16; ++j4) {
            float4 wv = wr[j4];
            h[4*j4]   = fmaf(xv, wv.x, h[4*j4]);
            h[4*j4+1] = fmaf(xv, wv.y, h[4*j4+1]);
            h[4*j4+2] = fmaf(xv, wv.z, h[4*j4+2]);
            h[4*j4+3] = fmaf(xv, wv.w, h[4*j4+3]);
        }
    }
#pragma unroll
    for (int j = 0; j < HID; ++j) row[j] = softplus_f(h[j]);

    float h2[HID];
#pragma unroll
    for (int j = 0; j < HID; ++j) h2[j] = sB2[j];
    for (int i = 0; i < HID; ++i) {
        float xv = row[i];
        const float4* wr = reinterpret_cast<const float4*>(sW2 + i * HID);
#pragma unroll
        for (int j4 = 0; j4 < 16; ++j4) {
            float4 wv = wr[j4];
            h2[4*j4]   = fmaf(xv, wv.x, h2[4*j4]);
            h2[4*j4+1] = fmaf(xv, wv.y, h2[4*j4+1]);
            h2[4*j4+2] = fmaf(xv, wv.z, h2[4*j4+2]);
            h2[4*j4+3] = fmaf(xv, wv.w, h2[4*j4+3]);
        }
    }
#pragma unroll
    for (int j = 0; j < HID; ++j) row[j] = softplus_f(h2[j]);

    float h3[OUT];
#pragma unroll
    for (int j = 0; j < OUT; ++j) h3[j] = sB3[j];
    for (int i = 0; i < HID; ++i) {
        float xv = row[i];
        const float4* wr = reinterpret_cast<const float4*>(sW3 + i * OUT);
#pragma unroll
        for (int j4 = 0; j4 < 8; ++j4) {
            float4 wv = wr[j4];
            h3[4*j4]   = fmaf(xv, wv.x, h3[4*j4]);
            h3[4*j4+1] = fmaf(xv, wv.y, h3[4*j4+1]);
            h3[4*j4+2] = fmaf(xv, wv.z, h3[4*j4+2]);
            h3[4*j4+3] = fmaf(xv, wv.w, h3[4*j4+3]);
        }
    }
    float o[OUT];
#pragma unroll
    for (int j = 0; j < OUT; ++j) o[j] = softplus_f(h3[j]);

    float4* orow = reinterpret_cast<float4*>(out + (size_t)(BATCH * NB * OUT) + (size_t)a * OUT);
#pragma unroll
    for (int j4 = 0; j4 < 8; ++j4)
        orow[j4] = make_float4(o[4*j4], o[4*j4+1], o[4*j4+2], o[4*j4+3]);

    int lane = tid & 31;
#pragma unroll
    for (int j = 0; j < OUT; ++j) {
        float v = o[j];
        v += __shfl_xor_sync(0xffffffffu, v, 16);
        v += __shfl_xor_sync(0xffffffffu, v, 8);
        v += __shfl_xor_sync(0xffffffffu, v, 4);
        v += __shfl_xor_sync(0xffffffffu, v, 2);
        v += __shfl_xor_sync(0xffffffffu, v, 1);
        if (lane == 0) atomicAdd(&sMsum[j], v);
    }
    __syncthreads();
    if (tid < OUT) atomicAdd(&g_asum[b * OUT + tid], sMsum[tid]);
}

__global__ void state_kernel(const float* __restrict__ state,
                             const float* __restrict__ uw1, const float* __restrict__ ub1,
                             const float* __restrict__ uw2, const float* __restrict__ ub2,
                             const float* __restrict__ uw3, const float* __restrict__ ub3,
                             float* __restrict__ out) {
    __shared__ float uin[96];
    __shared__ float h1s[HID];
    __shared__ float h2s[HID];
    int b = blockIdx.x;
    int j = threadIdx.x;
    if (j < 32) {
        uin[j] = g_bsum[b * OUT + j] * (1.0f / (float)NB);
        uin[32 + j] = g_asum[b * OUT + j] * (1.0f / (float)NA);
        uin[64 + j] = state[b * FDIM + j];
    }
    __syncthreads();
    float acc = ub1[j];
    for (int i = 0; i < 96; ++i) acc = fmaf(uin[i], uw1[i * HID + j], acc);
    h1s[j] = softplus_f(acc);
    __syncthreads();
    acc = ub2[j];
    for (int i = 0; i < HID; ++i) acc = fmaf(h1s[i], uw2[i * HID + j], acc);
    h2s[j] = softplus_f(acc);
    __syncthreads();
    if (j < OUT) {
        acc = ub3[j];
        for (int i = 0; i < HID; ++i) acc = fmaf(h2s[i], uw3[i * OUT + j], acc);
        out[(size_t)(BATCH * NB * OUT) + (size_t)(BATCH * NA * OUT) + b * OUT + j] = softplus_f(acc);
    }
}

extern "C" void kernel_launch(void* const* d_in, const int* in_sizes, int n_in,
                              void* d_out, int out_size) {
    const float* bonds = (const float*)d_in[0];
    const int* ia1 = (const int*)d_in[1];
    const int* ia2 = (const int*)d_in[2];
    const float* atoms = (const float*)d_in[3];
    const float* state = (const float*)d_in[4];
    const float* ew1 = (const float*)d_in[5];
    const float* eb1 = (const float*)d_in[6];
    const float* ew2 = (const float*)d_in[7];
    const float* eb2 = (const float*)d_in[8];
    const float* ew3 = (const float*)d_in[9];
    const float* eb3 = (const float*)d_in[10];
    const float* vw1 = (const float*)d_in[11];
    const float* vb1 = (const float*)d_in[12];
    const float* vw2 = (const float*)d_in[13];
    const float* vb2 = (const float*)d_in[14];
    const float* vw3 = (const float*)d_in[15];
    const float* vb3 = (const float*)d_in[16];
    const float* uw1 = (const float*)d_in[17];
    const float* ub1 = (const float*)d_in[18];
    const float* uw2 = (const float*)d_in[19];
    const float* ub2 = (const float*)d_in[20];
    const float* uw3 = (const float*)d_in[21];
    const float* ub3 = (const float*)d_in[22];
    float* out = (float*)d_out;

    const int AP_SMEM   = (64 * HID + 128 * 33) * (int)sizeof(float);
    const int ATOM_SMEM = (96 * HID + HID * HID + HID * OUT + 128 * 97
                           + HID + HID + OUT + OUT) * (int)sizeof(float);

    cudaFuncSetAttribute(ap_kernel, cudaFuncAttributeMaxDynamicSharedMemorySize, AP_SMEM);
    cudaFuncSetAttribute(bond_kernel, cudaFuncAttributeMaxDynamicSharedMemorySize, BOND_SMEM);
    cudaFuncSetAttribute(atom_kernel, cudaFuncAttributeMaxDynamicSharedMemorySize, ATOM_SMEM);

    hbprep_kernel<<<1, 256>>>(state, ew1, eb1, ew2, ew3);                 // 0
    ap_kernel<<<(BATCH * NA) / 128, 128, AP_SMEM>>>(atoms, ew1);          // 1
    sep_kernel<<<1, 32>>>();                                              // 2
    bond_kernel<<<(BATCH * NB) / 128, 128, BOND_SMEM>>>(bonds, ia1, ia2, eb2, eb3, out);  // 3 (ncu target)
    atom_kernel<<<(BATCH * NA) / 128, 128, ATOM_SMEM>>>(atoms, state, vw1, vb1, vw2, vb2, vw3, vb3, out);
    state_kernel<<<BATCH, 64>>>(state, uw1, ub1, uw2, ub2, uw3, ub3, out);
}